// round 11
// baseline (speedup 1.0000x reference)
#include <cuda_runtime.h>
#include <cuda_fp16.h>

#define N_NODES 100000
#define N_EDGES 1600000
#define DIM 64
#define SCAN_CHUNK 1024
#define NCH ((N_NODES + SCAN_CHUNK - 1) / SCAN_CHUNK)   // 98
#define NTHREADS_SS (NCH * SCAN_CHUNK)                  // 100352

// scratch (allocation-free: device globals; zero-initialized at module load)
__device__ float  g_h[(size_t)N_NODES * DIM];   // (1+eps)*x + agg
__device__ float  g_t[(size_t)N_NODES * DIM];   // h@W1 + b1
__device__ __half g_x16[(size_t)N_NODES * DIM]; // fp16 copy of x (gather path)
__device__ float  g_sum[DIM];
__device__ float  g_sq[DIM];
__device__ int    g_deg[N_NODES];               // invariant: zero at entry (agg resets)
__device__ int    g_off[N_NODES];
__device__ int    g_cur[N_NODES];
__device__ int    g_dbin[256];                  // degree histogram (agg resets)
__device__ int    g_bincnt[257];                // counting-sort cursors (agg resets)
__device__ int    g_perm[N_NODES];              // nodes sorted by degree
__device__ unsigned long long g_state[NCH];     // scan totals + done flags (agg resets)
__device__ unsigned g_es[N_EDGES];              // (attr<<28) | src

#define PACK2(d, lo, hi)  asm("mov.b64 %0, {%1, %2};" : "=l"(d) : "f"(lo), "f"(hi))
#define UNPACK2(lo, hi, s) asm("mov.b64 {%0, %1}, %2;" : "=f"(lo), "=f"(hi) : "l"(s))
#define FMA2(acc, a, b)   asm("fma.rn.f32x2 %0, %1, %2, %0;" : "+l"(acc) : "l"(a), "l"(b))

// ---------------------------------------------------------------------------
// K0: prep (x -> fp16, 8 floats/thread) + histogram of dst (4 edges/thread).
// ---------------------------------------------------------------------------
__global__ void prephist_kernel(const float* __restrict__ x, const int* __restrict__ ei) {
    int i = blockIdx.x * 256 + threadIdx.x;
    if (i < N_NODES * DIM / 8) {
        float4 a = __ldg((const float4*)x + 2 * i);
        float4 b = __ldg((const float4*)x + 2 * i + 1);
        __half2 h0 = __floats2half2_rn(a.x, a.y);
        __half2 h1 = __floats2half2_rn(a.z, a.w);
        __half2 h2 = __floats2half2_rn(b.x, b.y);
        __half2 h3 = __floats2half2_rn(b.z, b.w);
        uint4 p;
        p.x = *(unsigned*)&h0; p.y = *(unsigned*)&h1;
        p.z = *(unsigned*)&h2; p.w = *(unsigned*)&h3;
        ((uint4*)g_x16)[i] = p;
    }
    if (i < N_EDGES / 4) {
        int4 d = ((const int4*)(ei + N_EDGES))[i];
        atomicAdd(&g_deg[d.x], 1);
        atomicAdd(&g_deg[d.y], 1);
        atomicAdd(&g_deg[d.z], 1);
        atomicAdd(&g_deg[d.w], 1);
    }
}

// ---------------------------------------------------------------------------
// K1: merged scan + counting-sort + scatter. 98 blocks x 1024, all resident.
// Phase A: block scan of g_deg, publish totals, poll predecessors, write
//          g_off/g_cur; build degree-bin histogram.
// Barrier: threadfence + done-flag; poll all 98.
// Phase B: scan bins; counting-sort node ids into g_perm (warp-aggregated
//          atomics); scatter edges (attr<<28|src) into CSR slots.
// ---------------------------------------------------------------------------
__global__ void __launch_bounds__(1024)
scanscatter_kernel(const int* __restrict__ ei, const int* __restrict__ ea) {
    __shared__ int warp_sums[32];
    __shared__ int s_tot[128];
    __shared__ int s_bin[256];
    __shared__ int s_binoff[256];
    __shared__ int s_aux[8];

    int b = blockIdx.x;
    int t = threadIdx.x;
    int idx = b * SCAN_CHUNK + t;
    int d = (idx < N_NODES) ? g_deg[idx] : 0;
    int lane = t & 31, wid = t >> 5;

    // --- per-block degree-bin histogram ---
    if (t < 256) s_bin[t] = 0;
    __syncthreads();
    if (idx < N_NODES) atomicAdd(&s_bin[min(d, 255)], 1);

    // --- block-wide inclusive scan of d ---
    int v = d;
    #pragma unroll
    for (int o = 1; o < 32; o <<= 1) {
        int u = __shfl_up_sync(0xFFFFFFFFu, v, o);
        if (lane >= o) v += u;
    }
    if (lane == 31) warp_sums[wid] = v;
    __syncthreads();
    if (wid == 0) {
        int s = warp_sums[lane];
        #pragma unroll
        for (int o = 1; o < 32; o <<= 1) {
            int u = __shfl_up_sync(0xFFFFFFFFu, s, o);
            if (lane >= o) s += u;
        }
        warp_sums[lane] = s;
    }
    __syncthreads();
    int incl  = v + (wid > 0 ? warp_sums[wid - 1] : 0);
    int total = warp_sums[31];

    // flush block's bin histogram to global
    if (t < 256 && s_bin[t] > 0) atomicAdd(&g_dbin[t], s_bin[t]);

    // publish total (payload in atomic word: no fence needed for phase A)
    if (t == 0)
        atomicExch(&g_state[b], ((unsigned long long)(unsigned)total << 32) | 1ull);

    if (b == 0 && t < DIM) { g_sum[t] = 0.0f; g_sq[t] = 0.0f; }

    // poll predecessors' totals in parallel
    if (t < 128) s_tot[t] = 0;
    __syncthreads();
    if (t < b) {
        unsigned long long st;
        do { st = *(volatile unsigned long long*)&g_state[t]; } while (!(st & 1ull));
        s_tot[t] = (int)(st >> 32);
    }
    __syncthreads();
    if (t < 64) s_tot[t] += s_tot[t + 64];
    __syncthreads();
    if (t < 32) {
        int s = s_tot[t] + s_tot[t + 32];
        #pragma unroll
        for (int o = 16; o > 0; o >>= 1) s += __shfl_down_sync(0xFFFFFFFFu, s, o);
        if (t == 0) s_tot[0] = s;
    }
    __syncthreads();
    int ex = s_tot[0] + incl - d;
    if (idx < N_NODES) { g_off[idx] = ex; g_cur[idx] = ex; }

    // --- grid barrier: g_cur / g_dbin must be globally visible ---
    __threadfence();
    __syncthreads();
    if (t == 0) atomicOr(&g_state[b], 2ull);
    if (t < NCH) {
        while (!(*(volatile unsigned long long*)&g_state[t] & 2ull)) {}
    }
    __syncthreads();

    // --- Phase B1: exclusive scan of 256 degree bins (L2 loads) ---
    int binval = 0, bincl = 0;
    if (t < 256) {
        binval = __ldcg(&g_dbin[t]);
        s_bin[t] = binval;
        bincl = binval;
        #pragma unroll
        for (int o = 1; o < 32; o <<= 1) {
            int u = __shfl_up_sync(0xFFFFFFFFu, bincl, o);
            if (lane >= o) bincl += u;
        }
        if (lane == 31) s_aux[wid] = bincl;   // wid 0..7
    }
    __syncthreads();
    if (t == 0) {
        int run = 0;
        #pragma unroll
        for (int i = 0; i < 8; i++) { int c = s_aux[i]; s_aux[i] = run; run += c; }
    }
    __syncthreads();
    if (t < 256) s_binoff[t] = bincl - binval + s_aux[t >> 5];
    __syncthreads();

    // --- Phase B2: counting-sort node ids into g_perm (warp-aggregated) ---
    {
        int bin = (idx < N_NODES) ? min(d, 255) : 256;   // sentinel bin for pad threads
        unsigned m = __match_any_sync(0xFFFFFFFFu, bin);
        int leader = __ffs(m) - 1;
        int rank = __popc(m & ((1u << lane) - 1u));
        int base = 0;
        if (lane == leader) base = atomicAdd(&g_bincnt[bin], __popc(m));
        base = __shfl_sync(0xFFFFFFFFu, base, leader);
        if (idx < N_NODES) g_perm[s_binoff[bin] + base + rank] = idx;
    }

    // --- Phase B3: scatter edges into CSR slots (strided over grid) ---
    for (int i = b * SCAN_CHUNK + t; i < N_EDGES / 4; i += NTHREADS_SS) {
        int4 s = ((const int4*)ei)[i];
        int4 dd = ((const int4*)(ei + N_EDGES))[i];
        int4 a = ((const int4*)ea)[i];
        int p0 = atomicAdd(&g_cur[dd.x], 1);
        int p1 = atomicAdd(&g_cur[dd.y], 1);
        int p2 = atomicAdd(&g_cur[dd.z], 1);
        int p3 = atomicAdd(&g_cur[dd.w], 1);
        g_es[p0] = (unsigned)s.x | ((unsigned)a.x << 28);
        g_es[p1] = (unsigned)s.y | ((unsigned)a.y << 28);
        g_es[p2] = (unsigned)s.z | ((unsigned)a.z << 28);
        g_es[p3] = (unsigned)s.w | ((unsigned)a.w << 28);
    }
}

// ---------------------------------------------------------------------------
// K2: aggregate — nodes processed in degree-sorted order (g_perm) so all
// 4 nodes in a warp have (near-)equal degree -> uniform loop counts.
// 8 lanes/node; per edge: 1 idx LDG + 1 LDG.128 fp16 gather + 1 LDS.128 fp16
// emb + HADD2/HMAX2 relu; fp16 accumulate per unroll-4 block. Self term fp32.
// Block 0 resets scan/sort scratch for the next replay.
// ---------------------------------------------------------------------------
__global__ void __launch_bounds__(256)
agg_kernel(const float* __restrict__ x, const float* __restrict__ emb,
           const float* __restrict__ eps) {
    __shared__ __align__(16) __half s_emb16[4 * DIM];
    s_emb16[threadIdx.x] = __float2half(emb[threadIdx.x]);   // 256 == 4*64

    if (blockIdx.x == 0) {
        if (threadIdx.x < NCH) g_state[threadIdx.x] = 0ull;
        if (threadIdx.x < 256) { g_dbin[threadIdx.x] = 0; g_bincnt[threadIdx.x] = 0; }
        if (threadIdx.x == 0) g_bincnt[256] = 0;
    }
    __syncthreads();

    int gt = blockIdx.x * 256 + threadIdx.x;
    int slot = gt >> 3;
    int lane = gt & 7;
    if (slot >= N_NODES) return;

    int n = g_perm[slot];
    int off = g_off[n];
    int deg = g_deg[n];
    if (lane == 0) g_deg[n] = 0;              // restore invariant for next run
    float s = 1.0f + __ldg(eps);

    const float4* xp = (const float4*)(x + (size_t)n * DIM + lane * 8);
    float4 accA = __ldg(xp);
    float4 accB = __ldg(xp + 1);
    accA.x *= s; accA.y *= s; accA.z *= s; accA.w *= s;
    accB.x *= s; accB.y *= s; accB.z *= s; accB.w *= s;

    const uint4* xb = (const uint4*)g_x16;          // 8 uint4 per 64-half row
    const uint4* eb = (const uint4*)s_emb16;        // 8 uint4 per attr row
    const __half2 zero2 = __float2half2_rn(0.0f);

    int j = 0;
    for (; j + 4 <= deg; j += 4) {
        unsigned p0 = __ldg(g_es + off + j);
        unsigned p1 = __ldg(g_es + off + j + 1);
        unsigned p2 = __ldg(g_es + off + j + 2);
        unsigned p3 = __ldg(g_es + off + j + 3);
        uint4 r0 = __ldg(xb + (size_t)(p0 & 0x0FFFFFFFu) * 8 + lane);
        uint4 r1 = __ldg(xb + (size_t)(p1 & 0x0FFFFFFFu) * 8 + lane);
        uint4 r2 = __ldg(xb + (size_t)(p2 & 0x0FFFFFFFu) * 8 + lane);
        uint4 r3 = __ldg(xb + (size_t)(p3 & 0x0FFFFFFFu) * 8 + lane);
        uint4 e0 = eb[(p0 >> 28) * 8 + lane];
        uint4 e1 = eb[(p1 >> 28) * 8 + lane];
        uint4 e2 = eb[(p2 >> 28) * 8 + lane];
        uint4 e3 = eb[(p3 >> 28) * 8 + lane];

        __half2 a16_0, a16_1, a16_2, a16_3;
        a16_0 = __hmax2(__hadd2(*(__half2*)&r0.x, *(__half2*)&e0.x), zero2);
        a16_1 = __hmax2(__hadd2(*(__half2*)&r0.y, *(__half2*)&e0.y), zero2);
        a16_2 = __hmax2(__hadd2(*(__half2*)&r0.z, *(__half2*)&e0.z), zero2);
        a16_3 = __hmax2(__hadd2(*(__half2*)&r0.w, *(__half2*)&e0.w), zero2);
        a16_0 = __hadd2(a16_0, __hmax2(__hadd2(*(__half2*)&r1.x, *(__half2*)&e1.x), zero2));
        a16_1 = __hadd2(a16_1, __hmax2(__hadd2(*(__half2*)&r1.y, *(__half2*)&e1.y), zero2));
        a16_2 = __hadd2(a16_2, __hmax2(__hadd2(*(__half2*)&r1.z, *(__half2*)&e1.z), zero2));
        a16_3 = __hadd2(a16_3, __hmax2(__hadd2(*(__half2*)&r1.w, *(__half2*)&e1.w), zero2));
        a16_0 = __hadd2(a16_0, __hmax2(__hadd2(*(__half2*)&r2.x, *(__half2*)&e2.x), zero2));
        a16_1 = __hadd2(a16_1, __hmax2(__hadd2(*(__half2*)&r2.y, *(__half2*)&e2.y), zero2));
        a16_2 = __hadd2(a16_2, __hmax2(__hadd2(*(__half2*)&r2.z, *(__half2*)&e2.z), zero2));
        a16_3 = __hadd2(a16_3, __hmax2(__hadd2(*(__half2*)&r2.w, *(__half2*)&e2.w), zero2));
        a16_0 = __hadd2(a16_0, __hmax2(__hadd2(*(__half2*)&r3.x, *(__half2*)&e3.x), zero2));
        a16_1 = __hadd2(a16_1, __hmax2(__hadd2(*(__half2*)&r3.y, *(__half2*)&e3.y), zero2));
        a16_2 = __hadd2(a16_2, __hmax2(__hadd2(*(__half2*)&r3.z, *(__half2*)&e3.z), zero2));
        a16_3 = __hadd2(a16_3, __hmax2(__hadd2(*(__half2*)&r3.w, *(__half2*)&e3.w), zero2));

        float2 f0 = __half22float2(a16_0);
        float2 f1 = __half22float2(a16_1);
        float2 f2 = __half22float2(a16_2);
        float2 f3 = __half22float2(a16_3);
        accA.x += f0.x; accA.y += f0.y; accA.z += f1.x; accA.w += f1.y;
        accB.x += f2.x; accB.y += f2.y; accB.z += f3.x; accB.w += f3.y;
    }
    for (; j < deg; j++) {
        unsigned p0 = __ldg(g_es + off + j);
        uint4 r0 = __ldg(xb + (size_t)(p0 & 0x0FFFFFFFu) * 8 + lane);
        uint4 e0 = eb[(p0 >> 28) * 8 + lane];
        __half2 m0 = __hmax2(__hadd2(*(__half2*)&r0.x, *(__half2*)&e0.x), zero2);
        __half2 m1 = __hmax2(__hadd2(*(__half2*)&r0.y, *(__half2*)&e0.y), zero2);
        __half2 m2 = __hmax2(__hadd2(*(__half2*)&r0.z, *(__half2*)&e0.z), zero2);
        __half2 m3 = __hmax2(__hadd2(*(__half2*)&r0.w, *(__half2*)&e0.w), zero2);
        float2 f0 = __half22float2(m0);
        float2 f1 = __half22float2(m1);
        float2 f2 = __half22float2(m2);
        float2 f3 = __half22float2(m3);
        accA.x += f0.x; accA.y += f0.y; accA.z += f1.x; accA.w += f1.y;
        accB.x += f2.x; accB.y += f2.y; accB.z += f3.x; accB.w += f3.y;
    }

    float4* hp = (float4*)(g_h + (size_t)n * DIM + lane * 8);
    hp[0] = accA;
    hp[1] = accB;
}

// ---------------------------------------------------------------------------
// K3/K4: 128x64 tile GEMM, 8x8 per thread, fma.rn.f32x2 inner loop.
// MODE 0: t = g_h @ W1 + b1, write g_t, accumulate column sum/sumsq
// MODE 1: out = relu(t*A + B) @ W2 + b2, BN affine computed from g_sum/g_sq
// ---------------------------------------------------------------------------
#define TILE_R    128
#define IN_STRIDE 132
#define SMEM_FLOATS (DIM * DIM + DIM * IN_STRIDE + 2 * DIM)   // 12672

template <int MODE>
__global__ void gemm_kernel(const float* __restrict__ W, const float* __restrict__ bias,
                            const float* __restrict__ gamma, const float* __restrict__ beta,
                            float* __restrict__ out_ext) {
    extern __shared__ float sm[];
    float* sW   = sm;                               // [64][64]
    float* sIn  = sm + DIM * DIM;                   // [64][IN_STRIDE] k-major
    float* sAff = sm + DIM * DIM + DIM * IN_STRIDE; // [2][64]

    const float* in  = (MODE == 0) ? g_h : g_t;
    float*       out = (MODE == 0) ? g_t : out_ext;

    int t  = threadIdx.x;            // 128 threads
    int r0 = blockIdx.x * TILE_R;

    #pragma unroll
    for (int i = 0; i < 8; i++)
        ((float4*)sW)[t + i * 128] = ((const float4*)W)[t + i * 128];

    if (MODE == 1) {
        if (t < DIM) {
            const float inv = 1.0f / (float)N_NODES;
            float mu  = g_sum[t] * inv;
            float var = g_sq[t] * inv - mu * mu;
            float a   = gamma[t] * rsqrtf(var + 1e-5f);
            sAff[t]       = a;
            sAff[DIM + t] = fmaf(-mu, a, beta[t]);
        }
        __syncthreads();
    }

    {
        int row = r0 + t;
        bool valid = row < N_NODES;
        const float4* rp = (const float4*)(in + (size_t)row * DIM);
        #pragma unroll
        for (int q = 0; q < 16; q++) {
            float4 v = valid ? __ldg(rp + q) : make_float4(0.f, 0.f, 0.f, 0.f);
            int k0 = q * 4;
            if (MODE == 1) {
                v.x = fmaxf(fmaf(v.x, sAff[k0 + 0], sAff[DIM + k0 + 0]), 0.0f);
                v.y = fmaxf(fmaf(v.y, sAff[k0 + 1], sAff[DIM + k0 + 1]), 0.0f);
                v.z = fmaxf(fmaf(v.z, sAff[k0 + 2], sAff[DIM + k0 + 2]), 0.0f);
                v.w = fmaxf(fmaf(v.w, sAff[k0 + 3], sAff[DIM + k0 + 3]), 0.0f);
            }
            sIn[(k0 + 0) * IN_STRIDE + t] = v.x;
            sIn[(k0 + 1) * IN_STRIDE + t] = v.y;
            sIn[(k0 + 2) * IN_STRIDE + t] = v.z;
            sIn[(k0 + 3) * IN_STRIDE + t] = v.w;
        }
    }
    __syncthreads();

    int rg = t >> 3;  // 0..15
    int cg = t & 7;   // 0..7

    unsigned long long acc2[8][4];
    #pragma unroll
    for (int i = 0; i < 8; i++)
        #pragma unroll
        for (int jp = 0; jp < 4; jp++) acc2[i][jp] = 0ull;

    #pragma unroll 2
    for (int k = 0; k < 64; k++) {
        float4 a0 = *(const float4*)(sIn + k * IN_STRIDE + rg * 8);
        float4 a1 = *(const float4*)(sIn + k * IN_STRIDE + rg * 8 + 4);
        float4 w0 = *(const float4*)(sW  + k * DIM + cg * 8);
        float4 w1 = *(const float4*)(sW  + k * DIM + cg * 8 + 4);
        unsigned long long w2[4];
        PACK2(w2[0], w0.x, w0.y);
        PACK2(w2[1], w0.z, w0.w);
        PACK2(w2[2], w1.x, w1.y);
        PACK2(w2[3], w1.z, w1.w);
        float av[8] = {a0.x, a0.y, a0.z, a0.w, a1.x, a1.y, a1.z, a1.w};
        #pragma unroll
        for (int i = 0; i < 8; i++) {
            unsigned long long ai;
            PACK2(ai, av[i], av[i]);
            #pragma unroll
            for (int jp = 0; jp < 4; jp++)
                FMA2(acc2[i][jp], ai, w2[jp]);
        }
    }

    float bs[8];
    #pragma unroll
    for (int j = 0; j < 8; j++) bs[j] = bias[cg * 8 + j];

    float csum[8], csq[8];
    #pragma unroll
    for (int j = 0; j < 8; j++) { csum[j] = 0.0f; csq[j] = 0.0f; }

    #pragma unroll
    for (int i = 0; i < 8; i++) {
        int row = r0 + rg * 8 + i;
        if (row < N_NODES) {
            float v[8];
            #pragma unroll
            for (int jp = 0; jp < 4; jp++) {
                float lo, hi;
                UNPACK2(lo, hi, acc2[i][jp]);
                v[2 * jp]     = lo + bs[2 * jp];
                v[2 * jp + 1] = hi + bs[2 * jp + 1];
            }
            if (MODE == 0) {
                #pragma unroll
                for (int j = 0; j < 8; j++) { csum[j] += v[j]; csq[j] += v[j] * v[j]; }
            }
            *(float4*)(out + (size_t)row * DIM + cg * 8)     = make_float4(v[0], v[1], v[2], v[3]);
            *(float4*)(out + (size_t)row * DIM + cg * 8 + 4) = make_float4(v[4], v[5], v[6], v[7]);
        }
    }

    if (MODE == 0) {
        __syncthreads();
        float* red = sIn;
        #pragma unroll
        for (int j = 0; j < 8; j++) {
            red[rg * 64 + cg * 8 + j]        = csum[j];
            red[(16 + rg) * 64 + cg * 8 + j] = csq[j];
        }
        __syncthreads();
        if (t < 64) {
            float s = 0.0f;
            #pragma unroll
            for (int g = 0; g < 16; g++) s += red[g * 64 + t];
            atomicAdd(&g_sum[t], s);
        } else {
            int c = t - 64;
            float s = 0.0f;
            #pragma unroll
            for (int g = 0; g < 16; g++) s += red[(16 + g) * 64 + c];
            atomicAdd(&g_sq[c], s);
        }
    }
}

// ---------------------------------------------------------------------------
extern "C" void kernel_launch(void* const* d_in, const int* in_sizes, int n_in,
                              void* d_out, int out_size) {
    const float* x     = (const float*)d_in[0];
    const float* emb   = (const float*)d_in[1];
    const float* eps   = (const float*)d_in[2];
    const float* W1    = (const float*)d_in[3];
    const float* b1    = (const float*)d_in[4];
    const float* gamma = (const float*)d_in[5];
    const float* beta  = (const float*)d_in[6];
    const float* W2    = (const float*)d_in[7];
    const float* b2    = (const float*)d_in[8];
    const int*   ei    = (const int*)d_in[9];
    const int*   ea    = (const int*)d_in[10];
    float*       out   = (float*)d_out;

    const int smem_bytes = SMEM_FLOATS * 4;  // 50688 > 48K: opt in
    cudaFuncSetAttribute(gemm_kernel<0>, cudaFuncAttributeMaxDynamicSharedMemorySize, smem_bytes);
    cudaFuncSetAttribute(gemm_kernel<1>, cudaFuncAttributeMaxDynamicSharedMemorySize, smem_bytes);

    prephist_kernel<<<(N_NODES * DIM / 8 + 255) / 256, 256>>>(x, ei);   // 3125 blocks
    scanscatter_kernel<<<NCH, SCAN_CHUNK>>>(ei, ea);                    // 98 blocks (resident)
    agg_kernel<<<(N_NODES * 8 + 255) / 256, 256>>>(x, emb, eps);        // 3125 blocks
    const int gblocks = (N_NODES + TILE_R - 1) / TILE_R;                // 782
    gemm_kernel<0><<<gblocks, 128, smem_bytes>>>(W1, b1, nullptr, nullptr, nullptr);
    gemm_kernel<1><<<gblocks, 128, smem_bytes>>>(W2, b2, gamma, beta, out);
}

// round 12
// speedup vs baseline: 1.1691x; 1.1691x over previous
#include <cuda_runtime.h>
#include <cuda_fp16.h>

#define N_NODES 100000
#define N_EDGES 1600000
#define DIM 64
#define SCAN_CHUNK 1024
#define NCH ((N_NODES + SCAN_CHUNK - 1) / SCAN_CHUNK)   // 98

// scratch (allocation-free: device globals; zero-initialized at module load)
__device__ float  g_h[(size_t)N_NODES * DIM];   // (1+eps)*x + agg
__device__ float  g_t[(size_t)N_NODES * DIM];   // h@W1 + b1
__device__ __half g_x16[(size_t)N_NODES * DIM]; // fp16 copy of x (gather path)
__device__ float  g_sum[DIM];
__device__ float  g_sq[DIM];
__device__ int    g_deg[N_NODES];               // invariant: zero at entry (agg resets)
__device__ int    g_off[N_NODES];
__device__ int    g_cur[N_NODES];
__device__ unsigned long long g_state[NCH];     // invariant: zero at entry (scatter resets)
__device__ unsigned g_es[N_EDGES];              // (attr<<28) | src

#define PACK2(d, lo, hi)  asm("mov.b64 %0, {%1, %2};" : "=l"(d) : "f"(lo), "f"(hi))
#define UNPACK2(lo, hi, s) asm("mov.b64 {%0, %1}, %2;" : "=f"(lo), "=f"(hi) : "l"(s))
#define FMA2(acc, a, b)   asm("fma.rn.f32x2 %0, %1, %2, %0;" : "+l"(acc) : "l"(a), "l"(b))

// ---------------------------------------------------------------------------
// K0: prep (x -> fp16, 8 floats/thread) + histogram of dst (4 edges/thread).
// ---------------------------------------------------------------------------
__global__ void prephist_kernel(const float* __restrict__ x, const int* __restrict__ ei) {
    int i = blockIdx.x * 256 + threadIdx.x;
    if (i < N_NODES * DIM / 8) {
        float4 a = __ldg((const float4*)x + 2 * i);
        float4 b = __ldg((const float4*)x + 2 * i + 1);
        __half2 h0 = __floats2half2_rn(a.x, a.y);
        __half2 h1 = __floats2half2_rn(a.z, a.w);
        __half2 h2 = __floats2half2_rn(b.x, b.y);
        __half2 h3 = __floats2half2_rn(b.z, b.w);
        uint4 p;
        p.x = *(unsigned*)&h0; p.y = *(unsigned*)&h1;
        p.z = *(unsigned*)&h2; p.w = *(unsigned*)&h3;
        ((uint4*)g_x16)[i] = p;
    }
    if (i < N_EDGES / 4) {
        int4 d = ((const int4*)(ei + N_EDGES))[i];
        atomicAdd(&g_deg[d.x], 1);
        atomicAdd(&g_deg[d.y], 1);
        atomicAdd(&g_deg[d.z], 1);
        atomicAdd(&g_deg[d.w], 1);
    }
}

// ---------------------------------------------------------------------------
// K1: single-launch scan; block publishes total, polls predecessors in
// parallel (one hop). Block 0 zeroes BN accumulators. 98 blocks resident.
// ---------------------------------------------------------------------------
__global__ void scan_kernel() {
    __shared__ int warp_sums[32];
    __shared__ int s_tot[128];
    int b = blockIdx.x;
    int idx = b * SCAN_CHUNK + threadIdx.x;
    int d = (idx < N_NODES) ? g_deg[idx] : 0;

    int v = d;
    int lane = threadIdx.x & 31, wid = threadIdx.x >> 5;
    #pragma unroll
    for (int o = 1; o < 32; o <<= 1) {
        int t = __shfl_up_sync(0xFFFFFFFFu, v, o);
        if (lane >= o) v += t;
    }
    if (lane == 31) warp_sums[wid] = v;
    __syncthreads();
    if (wid == 0) {
        int s = warp_sums[lane];
        #pragma unroll
        for (int o = 1; o < 32; o <<= 1) {
            int t = __shfl_up_sync(0xFFFFFFFFu, s, o);
            if (lane >= o) s += t;
        }
        warp_sums[lane] = s;
    }
    __syncthreads();
    int incl  = v + (wid > 0 ? warp_sums[wid - 1] : 0);
    int total = warp_sums[31];

    if (threadIdx.x == 0)
        atomicExch(&g_state[b], ((unsigned long long)(unsigned)total << 32) | 1ull);

    if (b == 0 && threadIdx.x < DIM) { g_sum[threadIdx.x] = 0.0f; g_sq[threadIdx.x] = 0.0f; }

    if (threadIdx.x < 128) s_tot[threadIdx.x] = 0;
    __syncthreads();
    if ((int)threadIdx.x < b) {
        unsigned long long st;
        do { st = *(volatile unsigned long long*)&g_state[threadIdx.x]; } while (!(st & 1ull));
        s_tot[threadIdx.x] = (int)(st >> 32);
    }
    __syncthreads();
    if (threadIdx.x < 64) s_tot[threadIdx.x] += s_tot[threadIdx.x + 64];
    __syncthreads();
    if (threadIdx.x < 32) {
        int s = s_tot[threadIdx.x] + s_tot[threadIdx.x + 32];
        #pragma unroll
        for (int o = 16; o > 0; o >>= 1) s += __shfl_down_sync(0xFFFFFFFFu, s, o);
        if (threadIdx.x == 0) s_tot[0] = s;
    }
    __syncthreads();
    int ex = s_tot[0] + incl - d;
    if (idx < N_NODES) { g_off[idx] = ex; g_cur[idx] = ex; }
}

// ---------------------------------------------------------------------------
// K2: scatter packed (attr,src) — 4 edges/thread; blk0 resets g_state
// ---------------------------------------------------------------------------
__global__ void scatter_kernel(const int* __restrict__ ei, const int* __restrict__ ea) {
    if (blockIdx.x == 0 && threadIdx.x < NCH) g_state[threadIdx.x] = 0ull;
    int i = blockIdx.x * 256 + threadIdx.x;       // int4 index
    if (i >= N_EDGES / 4) return;
    int4 s = ((const int4*)ei)[i];
    int4 d = ((const int4*)(ei + N_EDGES))[i];
    int4 a = ((const int4*)ea)[i];
    int p0 = atomicAdd(&g_cur[d.x], 1);
    int p1 = atomicAdd(&g_cur[d.y], 1);
    int p2 = atomicAdd(&g_cur[d.z], 1);
    int p3 = atomicAdd(&g_cur[d.w], 1);
    g_es[p0] = (unsigned)s.x | ((unsigned)a.x << 28);
    g_es[p1] = (unsigned)s.y | ((unsigned)a.y << 28);
    g_es[p2] = (unsigned)s.z | ((unsigned)a.z << 28);
    g_es[p3] = (unsigned)s.w | ((unsigned)a.w << 28);
}

// ---------------------------------------------------------------------------
// K3: aggregate — 8 lanes/node. Per edge: 1 index LDG + 1 LDG.128 fp16 gather
// + 1 LDS.128 fp16 emb + HADD2/HMAX2 relu; fp16 accumulate per unroll-4
// block, converted to fp32 once per block. Self term exact fp32.
// ---------------------------------------------------------------------------
__global__ void __launch_bounds__(256)
agg_kernel(const float* __restrict__ x, const float* __restrict__ emb,
           const float* __restrict__ eps) {
    __shared__ __align__(16) __half s_emb16[4 * DIM];
    s_emb16[threadIdx.x] = __float2half(emb[threadIdx.x]);   // 256 == 4*64
    __syncthreads();

    int gt = blockIdx.x * 256 + threadIdx.x;
    int n = gt >> 3;
    int lane = gt & 7;
    if (n >= N_NODES) return;

    int off = g_off[n];
    int deg = g_deg[n];
    if (lane == 0) g_deg[n] = 0;              // restore invariant for next run
    float s = 1.0f + __ldg(eps);

    const float4* xp = (const float4*)(x + (size_t)n * DIM + lane * 8);
    float4 accA = __ldg(xp);
    float4 accB = __ldg(xp + 1);
    accA.x *= s; accA.y *= s; accA.z *= s; accA.w *= s;
    accB.x *= s; accB.y *= s; accB.z *= s; accB.w *= s;

    const uint4* xb = (const uint4*)g_x16;          // 8 uint4 per 64-half row
    const uint4* eb = (const uint4*)s_emb16;        // 8 uint4 per attr row
    const __half2 zero2 = __float2half2_rn(0.0f);

    int j = 0;
    for (; j + 4 <= deg; j += 4) {
        unsigned p0 = __ldg(g_es + off + j);
        unsigned p1 = __ldg(g_es + off + j + 1);
        unsigned p2 = __ldg(g_es + off + j + 2);
        unsigned p3 = __ldg(g_es + off + j + 3);
        uint4 r0 = __ldg(xb + (size_t)(p0 & 0x0FFFFFFFu) * 8 + lane);
        uint4 r1 = __ldg(xb + (size_t)(p1 & 0x0FFFFFFFu) * 8 + lane);
        uint4 r2 = __ldg(xb + (size_t)(p2 & 0x0FFFFFFFu) * 8 + lane);
        uint4 r3 = __ldg(xb + (size_t)(p3 & 0x0FFFFFFFu) * 8 + lane);
        uint4 e0 = eb[(p0 >> 28) * 8 + lane];
        uint4 e1 = eb[(p1 >> 28) * 8 + lane];
        uint4 e2 = eb[(p2 >> 28) * 8 + lane];
        uint4 e3 = eb[(p3 >> 28) * 8 + lane];

        __half2 a16_0, a16_1, a16_2, a16_3;
        a16_0 = __hmax2(__hadd2(*(__half2*)&r0.x, *(__half2*)&e0.x), zero2);
        a16_1 = __hmax2(__hadd2(*(__half2*)&r0.y, *(__half2*)&e0.y), zero2);
        a16_2 = __hmax2(__hadd2(*(__half2*)&r0.z, *(__half2*)&e0.z), zero2);
        a16_3 = __hmax2(__hadd2(*(__half2*)&r0.w, *(__half2*)&e0.w), zero2);
        a16_0 = __hadd2(a16_0, __hmax2(__hadd2(*(__half2*)&r1.x, *(__half2*)&e1.x), zero2));
        a16_1 = __hadd2(a16_1, __hmax2(__hadd2(*(__half2*)&r1.y, *(__half2*)&e1.y), zero2));
        a16_2 = __hadd2(a16_2, __hmax2(__hadd2(*(__half2*)&r1.z, *(__half2*)&e1.z), zero2));
        a16_3 = __hadd2(a16_3, __hmax2(__hadd2(*(__half2*)&r1.w, *(__half2*)&e1.w), zero2));
        a16_0 = __hadd2(a16_0, __hmax2(__hadd2(*(__half2*)&r2.x, *(__half2*)&e2.x), zero2));
        a16_1 = __hadd2(a16_1, __hmax2(__hadd2(*(__half2*)&r2.y, *(__half2*)&e2.y), zero2));
        a16_2 = __hadd2(a16_2, __hmax2(__hadd2(*(__half2*)&r2.z, *(__half2*)&e2.z), zero2));
        a16_3 = __hadd2(a16_3, __hmax2(__hadd2(*(__half2*)&r2.w, *(__half2*)&e2.w), zero2));
        a16_0 = __hadd2(a16_0, __hmax2(__hadd2(*(__half2*)&r3.x, *(__half2*)&e3.x), zero2));
        a16_1 = __hadd2(a16_1, __hmax2(__hadd2(*(__half2*)&r3.y, *(__half2*)&e3.y), zero2));
        a16_2 = __hadd2(a16_2, __hmax2(__hadd2(*(__half2*)&r3.z, *(__half2*)&e3.z), zero2));
        a16_3 = __hadd2(a16_3, __hmax2(__hadd2(*(__half2*)&r3.w, *(__half2*)&e3.w), zero2));

        float2 f0 = __half22float2(a16_0);
        float2 f1 = __half22float2(a16_1);
        float2 f2 = __half22float2(a16_2);
        float2 f3 = __half22float2(a16_3);
        accA.x += f0.x; accA.y += f0.y; accA.z += f1.x; accA.w += f1.y;
        accB.x += f2.x; accB.y += f2.y; accB.z += f3.x; accB.w += f3.y;
    }
    for (; j < deg; j++) {
        unsigned p0 = __ldg(g_es + off + j);
        uint4 r0 = __ldg(xb + (size_t)(p0 & 0x0FFFFFFFu) * 8 + lane);
        uint4 e0 = eb[(p0 >> 28) * 8 + lane];
        __half2 m0 = __hmax2(__hadd2(*(__half2*)&r0.x, *(__half2*)&e0.x), zero2);
        __half2 m1 = __hmax2(__hadd2(*(__half2*)&r0.y, *(__half2*)&e0.y), zero2);
        __half2 m2 = __hmax2(__hadd2(*(__half2*)&r0.z, *(__half2*)&e0.z), zero2);
        __half2 m3 = __hmax2(__hadd2(*(__half2*)&r0.w, *(__half2*)&e0.w), zero2);
        float2 f0 = __half22float2(m0);
        float2 f1 = __half22float2(m1);
        float2 f2 = __half22float2(m2);
        float2 f3 = __half22float2(m3);
        accA.x += f0.x; accA.y += f0.y; accA.z += f1.x; accA.w += f1.y;
        accB.x += f2.x; accB.y += f2.y; accB.z += f3.x; accB.w += f3.y;
    }

    float4* hp = (float4*)(g_h + (size_t)n * DIM + lane * 8);
    hp[0] = accA;
    hp[1] = accB;
}

// ---------------------------------------------------------------------------
// K4/K5: 128x64 tile GEMM, 256 threads, 8 rows x 4 cols per thread,
// fma.rn.f32x2 inner loop. 32 warps/SM at 4 blocks (50% occupancy).
// MODE 0: t = g_h @ W1 + b1, write g_t, accumulate column sum/sumsq
// MODE 1: out = relu(t*A + B) @ W2 + b2, BN affine computed from g_sum/g_sq
// ---------------------------------------------------------------------------
#define TILE_R    128
#define IN_STRIDE 132
#define SMEM_FLOATS (DIM * DIM + DIM * IN_STRIDE + 2 * DIM)   // 12672

template <int MODE>
__global__ void __launch_bounds__(256)
gemm_kernel(const float* __restrict__ W, const float* __restrict__ bias,
            const float* __restrict__ gamma, const float* __restrict__ beta,
            float* __restrict__ out_ext) {
    extern __shared__ float sm[];
    float* sW   = sm;                               // [64][64]
    float* sIn  = sm + DIM * DIM;                   // [64][IN_STRIDE] k-major
    float* sAff = sm + DIM * DIM + DIM * IN_STRIDE; // [2][64]

    const float* in  = (MODE == 0) ? g_h : g_t;
    float*       out = (MODE == 0) ? g_t : out_ext;

    int t  = threadIdx.x;            // 256 threads
    int r0 = blockIdx.x * TILE_R;

    #pragma unroll
    for (int i = 0; i < 4; i++)
        ((float4*)sW)[t + i * 256] = ((const float4*)W)[t + i * 256];

    if (MODE == 1) {
        if (t < DIM) {
            const float inv = 1.0f / (float)N_NODES;
            float mu  = g_sum[t] * inv;
            float var = g_sq[t] * inv - mu * mu;
            float a   = gamma[t] * rsqrtf(var + 1e-5f);
            sAff[t]       = a;
            sAff[DIM + t] = fmaf(-mu, a, beta[t]);
        }
        __syncthreads();
    }

    // load input tile transposed: thread pair (t>>1) owns one row; halves take
    // interleaved float4s (k0 = (2q+half)*4) so STS banks are disjoint.
    {
        int row_l = t >> 1;
        int half  = t & 1;
        int row   = r0 + row_l;
        bool valid = row < N_NODES;
        const float4* rp = (const float4*)(in + (size_t)row * DIM);
        #pragma unroll
        for (int q = 0; q < 8; q++) {
            int f4 = 2 * q + half;
            float4 v = valid ? __ldg(rp + f4) : make_float4(0.f, 0.f, 0.f, 0.f);
            int k0 = f4 * 4;
            if (MODE == 1) {
                v.x = fmaxf(fmaf(v.x, sAff[k0 + 0], sAff[DIM + k0 + 0]), 0.0f);
                v.y = fmaxf(fmaf(v.y, sAff[k0 + 1], sAff[DIM + k0 + 1]), 0.0f);
                v.z = fmaxf(fmaf(v.z, sAff[k0 + 2], sAff[DIM + k0 + 2]), 0.0f);
                v.w = fmaxf(fmaf(v.w, sAff[k0 + 3], sAff[DIM + k0 + 3]), 0.0f);
            }
            sIn[(k0 + 0) * IN_STRIDE + row_l] = v.x;
            sIn[(k0 + 1) * IN_STRIDE + row_l] = v.y;
            sIn[(k0 + 2) * IN_STRIDE + row_l] = v.z;
            sIn[(k0 + 3) * IN_STRIDE + row_l] = v.w;
        }
    }
    __syncthreads();

    int rg = t >> 4;   // 0..15 (row group of 8)
    int cg = t & 15;   // 0..15 (col group of 4)

    unsigned long long acc2[8][2];
    #pragma unroll
    for (int i = 0; i < 8; i++) { acc2[i][0] = 0ull; acc2[i][1] = 0ull; }

    #pragma unroll 4
    for (int k = 0; k < 64; k++) {
        float4 a0 = *(const float4*)(sIn + k * IN_STRIDE + rg * 8);
        float4 a1 = *(const float4*)(sIn + k * IN_STRIDE + rg * 8 + 4);
        float4 w  = *(const float4*)(sW  + k * DIM + cg * 4);
        unsigned long long w01, w23;
        PACK2(w01, w.x, w.y);
        PACK2(w23, w.z, w.w);
        float av[8] = {a0.x, a0.y, a0.z, a0.w, a1.x, a1.y, a1.z, a1.w};
        #pragma unroll
        for (int i = 0; i < 8; i++) {
            unsigned long long ai;
            PACK2(ai, av[i], av[i]);
            FMA2(acc2[i][0], ai, w01);
            FMA2(acc2[i][1], ai, w23);
        }
    }

    float bs[4];
    #pragma unroll
    for (int j = 0; j < 4; j++) bs[j] = bias[cg * 4 + j];

    float csum[4], csq[4];
    #pragma unroll
    for (int j = 0; j < 4; j++) { csum[j] = 0.0f; csq[j] = 0.0f; }

    #pragma unroll
    for (int i = 0; i < 8; i++) {
        int row = r0 + rg * 8 + i;
        if (row < N_NODES) {
            float v[4];
            UNPACK2(v[0], v[1], acc2[i][0]);
            UNPACK2(v[2], v[3], acc2[i][1]);
            #pragma unroll
            for (int j = 0; j < 4; j++) v[j] += bs[j];
            if (MODE == 0) {
                #pragma unroll
                for (int j = 0; j < 4; j++) { csum[j] += v[j]; csq[j] += v[j] * v[j]; }
            }
            *(float4*)(out + (size_t)row * DIM + cg * 4) = make_float4(v[0], v[1], v[2], v[3]);
        }
    }

    if (MODE == 0) {
        __syncthreads();          // done reading sIn; reuse as reduction scratch
        float* red = sIn;         // needs 2048 floats
        #pragma unroll
        for (int j = 0; j < 4; j++) {
            red[rg * 64 + cg * 4 + j]        = csum[j];
            red[(16 + rg) * 64 + cg * 4 + j] = csq[j];
        }
        __syncthreads();
        if (t < 64) {
            float s = 0.0f;
            #pragma unroll
            for (int g = 0; g < 16; g++) s += red[g * 64 + t];
            atomicAdd(&g_sum[t], s);
        } else if (t < 128) {
            int c = t - 64;
            float s = 0.0f;
            #pragma unroll
            for (int g = 0; g < 16; g++) s += red[(16 + g) * 64 + c];
            atomicAdd(&g_sq[c], s);
        }
    }
}

// ---------------------------------------------------------------------------
extern "C" void kernel_launch(void* const* d_in, const int* in_sizes, int n_in,
                              void* d_out, int out_size) {
    const float* x     = (const float*)d_in[0];
    const float* emb   = (const float*)d_in[1];
    const float* eps   = (const float*)d_in[2];
    const float* W1    = (const float*)d_in[3];
    const float* b1    = (const float*)d_in[4];
    const float* gamma = (const float*)d_in[5];
    const float* beta  = (const float*)d_in[6];
    const float* W2    = (const float*)d_in[7];
    const float* b2    = (const float*)d_in[8];
    const int*   ei    = (const int*)d_in[9];
    const int*   ea    = (const int*)d_in[10];
    float*       out   = (float*)d_out;

    const int smem_bytes = SMEM_FLOATS * 4;  // 50688 > 48K: opt in
    cudaFuncSetAttribute(gemm_kernel<0>, cudaFuncAttributeMaxDynamicSharedMemorySize, smem_bytes);
    cudaFuncSetAttribute(gemm_kernel<1>, cudaFuncAttributeMaxDynamicSharedMemorySize, smem_bytes);

    prephist_kernel<<<(N_NODES * DIM / 8 + 255) / 256, 256>>>(x, ei);   // 3125 blocks
    scan_kernel<<<NCH, SCAN_CHUNK>>>();
    scatter_kernel<<<(N_EDGES / 4 + 255) / 256, 256>>>(ei, ea);         // 1563 blocks
    agg_kernel<<<(N_NODES * 8 + 255) / 256, 256>>>(x, emb, eps);        // 3125 blocks
    const int gblocks = (N_NODES + TILE_R - 1) / TILE_R;                // 782
    gemm_kernel<0><<<gblocks, 256, smem_bytes>>>(W1, b1, nullptr, nullptr, nullptr);
    gemm_kernel<1><<<gblocks, 256, smem_bytes>>>(W2, b2, gamma, beta, out);
}

// round 13
// speedup vs baseline: 1.1731x; 1.0034x over previous
#include <cuda_runtime.h>
#include <cuda_fp16.h>

#define N_NODES 100000
#define N_EDGES 1600000
#define DIM 64
#define SCAN_CHUNK 1024
#define NCH ((N_NODES + SCAN_CHUNK - 1) / SCAN_CHUNK)   // 98

// scratch (allocation-free: device globals; zero-initialized at module load)
__device__ float  g_h[(size_t)N_NODES * DIM];   // (1+eps)*x + agg
__device__ float  g_t[(size_t)N_NODES * DIM];   // h@W1 + b1
__device__ __half g_x16[(size_t)N_NODES * DIM]; // fp16 copy of x (gather path)
__device__ float  g_sum[DIM];
__device__ float  g_sq[DIM];
__device__ int    g_deg[N_NODES];               // invariant: zero at entry (agg resets)
__device__ int    g_off[N_NODES];
__device__ int    g_cur[N_NODES];
__device__ unsigned long long g_state[NCH];     // invariant: zero at entry (scatter resets)
__device__ unsigned g_es[N_EDGES];              // (attr<<28) | src

#define PACK2(d, lo, hi)  asm("mov.b64 %0, {%1, %2};" : "=l"(d) : "f"(lo), "f"(hi))
#define UNPACK2(lo, hi, s) asm("mov.b64 {%0, %1}, %2;" : "=f"(lo), "=f"(hi) : "l"(s))
#define FMA2(acc, a, b)   asm("fma.rn.f32x2 %0, %1, %2, %0;" : "+l"(acc) : "l"(a), "l"(b))

// ---------------------------------------------------------------------------
// K0: prep (x -> fp16, 8 floats/thread) + histogram of dst (4 edges/thread).
// ---------------------------------------------------------------------------
__global__ void prephist_kernel(const float* __restrict__ x, const int* __restrict__ ei) {
    int i = blockIdx.x * 256 + threadIdx.x;
    if (i < N_NODES * DIM / 8) {
        float4 a = __ldg((const float4*)x + 2 * i);
        float4 b = __ldg((const float4*)x + 2 * i + 1);
        __half2 h0 = __floats2half2_rn(a.x, a.y);
        __half2 h1 = __floats2half2_rn(a.z, a.w);
        __half2 h2 = __floats2half2_rn(b.x, b.y);
        __half2 h3 = __floats2half2_rn(b.z, b.w);
        uint4 p;
        p.x = *(unsigned*)&h0; p.y = *(unsigned*)&h1;
        p.z = *(unsigned*)&h2; p.w = *(unsigned*)&h3;
        ((uint4*)g_x16)[i] = p;
    }
    if (i < N_EDGES / 4) {
        int4 d = ((const int4*)(ei + N_EDGES))[i];
        atomicAdd(&g_deg[d.x], 1);
        atomicAdd(&g_deg[d.y], 1);
        atomicAdd(&g_deg[d.z], 1);
        atomicAdd(&g_deg[d.w], 1);
    }
}

// ---------------------------------------------------------------------------
// K1: single-launch scan; block publishes total, polls predecessors in
// parallel (one hop). Block 0 zeroes BN accumulators. 98 blocks resident.
// ---------------------------------------------------------------------------
__global__ void scan_kernel() {
    __shared__ int warp_sums[32];
    __shared__ int s_tot[128];
    int b = blockIdx.x;
    int idx = b * SCAN_CHUNK + threadIdx.x;
    int d = (idx < N_NODES) ? g_deg[idx] : 0;

    int v = d;
    int lane = threadIdx.x & 31, wid = threadIdx.x >> 5;
    #pragma unroll
    for (int o = 1; o < 32; o <<= 1) {
        int t = __shfl_up_sync(0xFFFFFFFFu, v, o);
        if (lane >= o) v += t;
    }
    if (lane == 31) warp_sums[wid] = v;
    __syncthreads();
    if (wid == 0) {
        int s = warp_sums[lane];
        #pragma unroll
        for (int o = 1; o < 32; o <<= 1) {
            int t = __shfl_up_sync(0xFFFFFFFFu, s, o);
            if (lane >= o) s += t;
        }
        warp_sums[lane] = s;
    }
    __syncthreads();
    int incl  = v + (wid > 0 ? warp_sums[wid - 1] : 0);
    int total = warp_sums[31];

    if (threadIdx.x == 0)
        atomicExch(&g_state[b], ((unsigned long long)(unsigned)total << 32) | 1ull);

    if (b == 0 && threadIdx.x < DIM) { g_sum[threadIdx.x] = 0.0f; g_sq[threadIdx.x] = 0.0f; }

    if (threadIdx.x < 128) s_tot[threadIdx.x] = 0;
    __syncthreads();
    if ((int)threadIdx.x < b) {
        unsigned long long st;
        do { st = *(volatile unsigned long long*)&g_state[threadIdx.x]; } while (!(st & 1ull));
        s_tot[threadIdx.x] = (int)(st >> 32);
    }
    __syncthreads();
    if (threadIdx.x < 64) s_tot[threadIdx.x] += s_tot[threadIdx.x + 64];
    __syncthreads();
    if (threadIdx.x < 32) {
        int s = s_tot[threadIdx.x] + s_tot[threadIdx.x + 32];
        #pragma unroll
        for (int o = 16; o > 0; o >>= 1) s += __shfl_down_sync(0xFFFFFFFFu, s, o);
        if (threadIdx.x == 0) s_tot[0] = s;
    }
    __syncthreads();
    int ex = s_tot[0] + incl - d;
    if (idx < N_NODES) { g_off[idx] = ex; g_cur[idx] = ex; }
}

// ---------------------------------------------------------------------------
// K2: scatter packed (attr,src) — 4 edges/thread; blk0 resets g_state
// ---------------------------------------------------------------------------
__global__ void scatter_kernel(const int* __restrict__ ei, const int* __restrict__ ea) {
    if (blockIdx.x == 0 && threadIdx.x < NCH) g_state[threadIdx.x] = 0ull;
    int i = blockIdx.x * 256 + threadIdx.x;       // int4 index
    if (i >= N_EDGES / 4) return;
    int4 s = ((const int4*)ei)[i];
    int4 d = ((const int4*)(ei + N_EDGES))[i];
    int4 a = ((const int4*)ea)[i];
    int p0 = atomicAdd(&g_cur[d.x], 1);
    int p1 = atomicAdd(&g_cur[d.y], 1);
    int p2 = atomicAdd(&g_cur[d.z], 1);
    int p3 = atomicAdd(&g_cur[d.w], 1);
    g_es[p0] = (unsigned)s.x | ((unsigned)a.x << 28);
    g_es[p1] = (unsigned)s.y | ((unsigned)a.y << 28);
    g_es[p2] = (unsigned)s.z | ((unsigned)a.z << 28);
    g_es[p3] = (unsigned)s.w | ((unsigned)a.w << 28);
}

// ---------------------------------------------------------------------------
// K3: aggregate — 8 lanes/node. Per edge: 1 index LDG + 1 LDG.128 fp16 gather
// + 1 LDS.128 fp16 emb + HADD2/HMAX2 relu; fp16 accumulate per unroll-4
// block, converted to fp32 once per block. Self term exact fp32.
// ---------------------------------------------------------------------------
__global__ void __launch_bounds__(256)
agg_kernel(const float* __restrict__ x, const float* __restrict__ emb,
           const float* __restrict__ eps) {
    __shared__ __align__(16) __half s_emb16[4 * DIM];
    s_emb16[threadIdx.x] = __float2half(emb[threadIdx.x]);   // 256 == 4*64
    __syncthreads();

    int gt = blockIdx.x * 256 + threadIdx.x;
    int n = gt >> 3;
    int lane = gt & 7;
    if (n >= N_NODES) return;

    int off = g_off[n];
    int deg = g_deg[n];
    if (lane == 0) g_deg[n] = 0;              // restore invariant for next run
    float s = 1.0f + __ldg(eps);

    const float4* xp = (const float4*)(x + (size_t)n * DIM + lane * 8);
    float4 accA = __ldg(xp);
    float4 accB = __ldg(xp + 1);
    accA.x *= s; accA.y *= s; accA.z *= s; accA.w *= s;
    accB.x *= s; accB.y *= s; accB.z *= s; accB.w *= s;

    const uint4* xb = (const uint4*)g_x16;          // 8 uint4 per 64-half row
    const uint4* eb = (const uint4*)s_emb16;        // 8 uint4 per attr row
    const __half2 zero2 = __float2half2_rn(0.0f);

    int j = 0;
    for (; j + 4 <= deg; j += 4) {
        unsigned p0 = __ldg(g_es + off + j);
        unsigned p1 = __ldg(g_es + off + j + 1);
        unsigned p2 = __ldg(g_es + off + j + 2);
        unsigned p3 = __ldg(g_es + off + j + 3);
        uint4 r0 = __ldg(xb + (size_t)(p0 & 0x0FFFFFFFu) * 8 + lane);
        uint4 r1 = __ldg(xb + (size_t)(p1 & 0x0FFFFFFFu) * 8 + lane);
        uint4 r2 = __ldg(xb + (size_t)(p2 & 0x0FFFFFFFu) * 8 + lane);
        uint4 r3 = __ldg(xb + (size_t)(p3 & 0x0FFFFFFFu) * 8 + lane);
        uint4 e0 = eb[(p0 >> 28) * 8 + lane];
        uint4 e1 = eb[(p1 >> 28) * 8 + lane];
        uint4 e2 = eb[(p2 >> 28) * 8 + lane];
        uint4 e3 = eb[(p3 >> 28) * 8 + lane];

        __half2 a16_0, a16_1, a16_2, a16_3;
        a16_0 = __hmax2(__hadd2(*(__half2*)&r0.x, *(__half2*)&e0.x), zero2);
        a16_1 = __hmax2(__hadd2(*(__half2*)&r0.y, *(__half2*)&e0.y), zero2);
        a16_2 = __hmax2(__hadd2(*(__half2*)&r0.z, *(__half2*)&e0.z), zero2);
        a16_3 = __hmax2(__hadd2(*(__half2*)&r0.w, *(__half2*)&e0.w), zero2);
        a16_0 = __hadd2(a16_0, __hmax2(__hadd2(*(__half2*)&r1.x, *(__half2*)&e1.x), zero2));
        a16_1 = __hadd2(a16_1, __hmax2(__hadd2(*(__half2*)&r1.y, *(__half2*)&e1.y), zero2));
        a16_2 = __hadd2(a16_2, __hmax2(__hadd2(*(__half2*)&r1.z, *(__half2*)&e1.z), zero2));
        a16_3 = __hadd2(a16_3, __hmax2(__hadd2(*(__half2*)&r1.w, *(__half2*)&e1.w), zero2));
        a16_0 = __hadd2(a16_0, __hmax2(__hadd2(*(__half2*)&r2.x, *(__half2*)&e2.x), zero2));
        a16_1 = __hadd2(a16_1, __hmax2(__hadd2(*(__half2*)&r2.y, *(__half2*)&e2.y), zero2));
        a16_2 = __hadd2(a16_2, __hmax2(__hadd2(*(__half2*)&r2.z, *(__half2*)&e2.z), zero2));
        a16_3 = __hadd2(a16_3, __hmax2(__hadd2(*(__half2*)&r2.w, *(__half2*)&e2.w), zero2));
        a16_0 = __hadd2(a16_0, __hmax2(__hadd2(*(__half2*)&r3.x, *(__half2*)&e3.x), zero2));
        a16_1 = __hadd2(a16_1, __hmax2(__hadd2(*(__half2*)&r3.y, *(__half2*)&e3.y), zero2));
        a16_2 = __hadd2(a16_2, __hmax2(__hadd2(*(__half2*)&r3.z, *(__half2*)&e3.z), zero2));
        a16_3 = __hadd2(a16_3, __hmax2(__hadd2(*(__half2*)&r3.w, *(__half2*)&e3.w), zero2));

        float2 f0 = __half22float2(a16_0);
        float2 f1 = __half22float2(a16_1);
        float2 f2 = __half22float2(a16_2);
        float2 f3 = __half22float2(a16_3);
        accA.x += f0.x; accA.y += f0.y; accA.z += f1.x; accA.w += f1.y;
        accB.x += f2.x; accB.y += f2.y; accB.z += f3.x; accB.w += f3.y;
    }
    for (; j < deg; j++) {
        unsigned p0 = __ldg(g_es + off + j);
        uint4 r0 = __ldg(xb + (size_t)(p0 & 0x0FFFFFFFu) * 8 + lane);
        uint4 e0 = eb[(p0 >> 28) * 8 + lane];
        __half2 m0 = __hmax2(__hadd2(*(__half2*)&r0.x, *(__half2*)&e0.x), zero2);
        __half2 m1 = __hmax2(__hadd2(*(__half2*)&r0.y, *(__half2*)&e0.y), zero2);
        __half2 m2 = __hmax2(__hadd2(*(__half2*)&r0.z, *(__half2*)&e0.z), zero2);
        __half2 m3 = __hmax2(__hadd2(*(__half2*)&r0.w, *(__half2*)&e0.w), zero2);
        float2 f0 = __half22float2(m0);
        float2 f1 = __half22float2(m1);
        float2 f2 = __half22float2(m2);
        float2 f3 = __half22float2(m3);
        accA.x += f0.x; accA.y += f0.y; accA.z += f1.x; accA.w += f1.y;
        accB.x += f2.x; accB.y += f2.y; accB.z += f3.x; accB.w += f3.y;
    }

    float4* hp = (float4*)(g_h + (size_t)n * DIM + lane * 8);
    hp[0] = accA;
    hp[1] = accB;
}

// ---------------------------------------------------------------------------
// K4/K5: 128x64 tile GEMM, 256 threads, 8 rows x 4 cols per thread,
// fma.rn.f32x2 inner loop. 32 warps/SM at 4 blocks (50% occupancy).
// MODE 0: t = g_h @ W1 + b1, write g_t, accumulate column sum/sumsq
// MODE 1: out = relu(t*A + B) @ W2 + b2, BN affine computed from g_sum/g_sq
// ---------------------------------------------------------------------------
#define TILE_R    128
#define IN_STRIDE 132
#define SMEM_FLOATS (DIM * DIM + DIM * IN_STRIDE + 2 * DIM)   // 12672

template <int MODE>
__global__ void __launch_bounds__(256)
gemm_kernel(const float* __restrict__ W, const float* __restrict__ bias,
            const float* __restrict__ gamma, const float* __restrict__ beta,
            float* __restrict__ out_ext) {
    extern __shared__ float sm[];
    float* sW   = sm;                               // [64][64]
    float* sIn  = sm + DIM * DIM;                   // [64][IN_STRIDE] k-major
    float* sAff = sm + DIM * DIM + DIM * IN_STRIDE; // [2][64]

    const float* in  = (MODE == 0) ? g_h : g_t;
    float*       out = (MODE == 0) ? g_t : out_ext;

    int t  = threadIdx.x;            // 256 threads
    int r0 = blockIdx.x * TILE_R;

    #pragma unroll
    for (int i = 0; i < 4; i++)
        ((float4*)sW)[t + i * 256] = ((const float4*)W)[t + i * 256];

    if (MODE == 1) {
        if (t < DIM) {
            const float inv = 1.0f / (float)N_NODES;
            float mu  = g_sum[t] * inv;
            float var = g_sq[t] * inv - mu * mu;
            float a   = gamma[t] * rsqrtf(var + 1e-5f);
            sAff[t]       = a;
            sAff[DIM + t] = fmaf(-mu, a, beta[t]);
        }
        __syncthreads();
    }

    // load input tile transposed: thread pair (t>>1) owns one row; halves take
    // interleaved float4s (k0 = (2q+half)*4) so STS banks are disjoint.
    {
        int row_l = t >> 1;
        int half  = t & 1;
        int row   = r0 + row_l;
        bool valid = row < N_NODES;
        const float4* rp = (const float4*)(in + (size_t)row * DIM);
        #pragma unroll
        for (int q = 0; q < 8; q++) {
            int f4 = 2 * q + half;
            float4 v = valid ? __ldg(rp + f4) : make_float4(0.f, 0.f, 0.f, 0.f);
            int k0 = f4 * 4;
            if (MODE == 1) {
                v.x = fmaxf(fmaf(v.x, sAff[k0 + 0], sAff[DIM + k0 + 0]), 0.0f);
                v.y = fmaxf(fmaf(v.y, sAff[k0 + 1], sAff[DIM + k0 + 1]), 0.0f);
                v.z = fmaxf(fmaf(v.z, sAff[k0 + 2], sAff[DIM + k0 + 2]), 0.0f);
                v.w = fmaxf(fmaf(v.w, sAff[k0 + 3], sAff[DIM + k0 + 3]), 0.0f);
            }
            sIn[(k0 + 0) * IN_STRIDE + row_l] = v.x;
            sIn[(k0 + 1) * IN_STRIDE + row_l] = v.y;
            sIn[(k0 + 2) * IN_STRIDE + row_l] = v.z;
            sIn[(k0 + 3) * IN_STRIDE + row_l] = v.w;
        }
    }
    __syncthreads();

    int rg = t >> 4;   // 0..15 (row group of 8)
    int cg = t & 15;   // 0..15 (col group of 4)

    unsigned long long acc2[8][2];
    #pragma unroll
    for (int i = 0; i < 8; i++) { acc2[i][0] = 0ull; acc2[i][1] = 0ull; }

    #pragma unroll 4
    for (int k = 0; k < 64; k++) {
        float4 a0 = *(const float4*)(sIn + k * IN_STRIDE + rg * 8);
        float4 a1 = *(const float4*)(sIn + k * IN_STRIDE + rg * 8 + 4);
        float4 w  = *(const float4*)(sW  + k * DIM + cg * 4);
        unsigned long long w01, w23;
        PACK2(w01, w.x, w.y);
        PACK2(w23, w.z, w.w);
        float av[8] = {a0.x, a0.y, a0.z, a0.w, a1.x, a1.y, a1.z, a1.w};
        #pragma unroll
        for (int i = 0; i < 8; i++) {
            unsigned long long ai;
            PACK2(ai, av[i], av[i]);
            FMA2(acc2[i][0], ai, w01);
            FMA2(acc2[i][1], ai, w23);
        }
    }

    float bs[4];
    #pragma unroll
    for (int j = 0; j < 4; j++) bs[j] = bias[cg * 4 + j];

    float csum[4], csq[4];
    #pragma unroll
    for (int j = 0; j < 4; j++) { csum[j] = 0.0f; csq[j] = 0.0f; }

    #pragma unroll
    for (int i = 0; i < 8; i++) {
        int row = r0 + rg * 8 + i;
        if (row < N_NODES) {
            float v[4];
            UNPACK2(v[0], v[1], acc2[i][0]);
            UNPACK2(v[2], v[3], acc2[i][1]);
            #pragma unroll
            for (int j = 0; j < 4; j++) v[j] += bs[j];
            if (MODE == 0) {
                #pragma unroll
                for (int j = 0; j < 4; j++) { csum[j] += v[j]; csq[j] += v[j] * v[j]; }
            }
            *(float4*)(out + (size_t)row * DIM + cg * 4) = make_float4(v[0], v[1], v[2], v[3]);
        }
    }

    if (MODE == 0) {
        __syncthreads();          // done reading sIn; reuse as reduction scratch
        float* red = sIn;         // needs 2048 floats
        #pragma unroll
        for (int j = 0; j < 4; j++) {
            red[rg * 64 + cg * 4 + j]        = csum[j];
            red[(16 + rg) * 64 + cg * 4 + j] = csq[j];
        }
        __syncthreads();
        if (t < 64) {
            float s = 0.0f;
            #pragma unroll
            for (int g = 0; g < 16; g++) s += red[g * 64 + t];
            atomicAdd(&g_sum[t], s);
        } else if (t < 128) {
            int c = t - 64;
            float s = 0.0f;
            #pragma unroll
            for (int g = 0; g < 16; g++) s += red[(16 + g) * 64 + c];
            atomicAdd(&g_sq[c], s);
        }
    }
}

// ---------------------------------------------------------------------------
extern "C" void kernel_launch(void* const* d_in, const int* in_sizes, int n_in,
                              void* d_out, int out_size) {
    const float* x     = (const float*)d_in[0];
    const float* emb   = (const float*)d_in[1];
    const float* eps   = (const float*)d_in[2];
    const float* W1    = (const float*)d_in[3];
    const float* b1    = (const float*)d_in[4];
    const float* gamma = (const float*)d_in[5];
    const float* beta  = (const float*)d_in[6];
    const float* W2    = (const float*)d_in[7];
    const float* b2    = (const float*)d_in[8];
    const int*   ei    = (const int*)d_in[9];
    const int*   ea    = (const int*)d_in[10];
    float*       out   = (float*)d_out;

    const int smem_bytes = SMEM_FLOATS * 4;  // 50688 > 48K: opt in
    cudaFuncSetAttribute(gemm_kernel<0>, cudaFuncAttributeMaxDynamicSharedMemorySize, smem_bytes);
    cudaFuncSetAttribute(gemm_kernel<1>, cudaFuncAttributeMaxDynamicSharedMemorySize, smem_bytes);

    prephist_kernel<<<(N_NODES * DIM / 8 + 255) / 256, 256>>>(x, ei);   // 3125 blocks
    scan_kernel<<<NCH, SCAN_CHUNK>>>();
    scatter_kernel<<<(N_EDGES / 4 + 255) / 256, 256>>>(ei, ea);         // 1563 blocks
    agg_kernel<<<(N_NODES * 8 + 255) / 256, 256>>>(x, emb, eps);        // 3125 blocks
    const int gblocks = (N_NODES + TILE_R - 1) / TILE_R;                // 782
    gemm_kernel<0><<<gblocks, 256, smem_bytes>>>(W1, b1, nullptr, nullptr, nullptr);
    gemm_kernel<1><<<gblocks, 256, smem_bytes>>>(W2, b2, gamma, beta, out);
}

// round 15
// speedup vs baseline: 1.2388x; 1.0560x over previous
#include <cuda_runtime.h>
#include <cuda_fp16.h>
#include <cstdint>

#define N_NODES 100000
#define N_EDGES 1600000
#define DIM 64
#define SCAN_CHUNK 1024
#define NCH 98
#define TILE_R 128

__device__ float  g_h[(size_t)N_NODES * DIM];
__device__ float  g_t[(size_t)N_NODES * DIM];
__device__ __half g_x16[(size_t)N_NODES * DIM];
__device__ uint2  g_wfrag[2 * 1024];                // per-lane B fragments, [which][s*8+j][lane]
__device__ float  g_sum[DIM];
__device__ float  g_sq[DIM];
__device__ int    g_deg[N_NODES];                   // zero at entry (agg resets)
__device__ int    g_off[N_NODES];
__device__ int    g_cur[N_NODES];
__device__ unsigned long long g_state[NCH];         // zero at entry (scatter resets)
__device__ unsigned g_es[N_EDGES];                  // (attr<<28) | src

__device__ __forceinline__ uint32_t smem_u32(const void* p) {
    uint32_t a;
    asm("{ .reg .u64 t; cvta.to.shared.u64 t, %1; cvt.u32.u64 %0, t; }" : "=r"(a) : "l"(p));
    return a;
}

// ---------------------------------------------------------------------------
// K0: prep — x->fp16 | dst histogram | W1/W2 -> per-lane mma B fragments.
// B frag layout (m16n8k16 row.col): lane g=lane>>2, tid4=lane&3, n=j*8+g;
//   b.x = half2(W[s*16+tid4*2][n],   W[s*16+tid4*2+1][n])
//   b.y = half2(W[s*16+tid4*2+8][n], W[s*16+tid4*2+9][n])
// ---------------------------------------------------------------------------
__global__ void prep_kernel(const float* __restrict__ x, const int* __restrict__ ei,
                            const float* __restrict__ W1, const float* __restrict__ W2) {
    int i = blockIdx.x * 256 + threadIdx.x;
    if (i < N_NODES * DIM / 8) {
        float4 a = __ldg((const float4*)x + 2 * i);
        float4 b = __ldg((const float4*)x + 2 * i + 1);
        __half2 h0 = __floats2half2_rn(a.x, a.y), h1 = __floats2half2_rn(a.z, a.w);
        __half2 h2 = __floats2half2_rn(b.x, b.y), h3 = __floats2half2_rn(b.z, b.w);
        uint4 p;
        p.x = *(unsigned*)&h0; p.y = *(unsigned*)&h1;
        p.z = *(unsigned*)&h2; p.w = *(unsigned*)&h3;
        ((uint4*)g_x16)[i] = p;
    }
    if (i < N_EDGES / 4) {
        int4 d = ((const int4*)(ei + N_EDGES))[i];
        atomicAdd(&g_deg[d.x], 1); atomicAdd(&g_deg[d.y], 1);
        atomicAdd(&g_deg[d.z], 1); atomicAdd(&g_deg[d.w], 1);
    }
    if (i < 2048) {
        int which = i >> 10, r = i & 1023;
        int s = r >> 8, rem = r & 255, j = rem >> 5, lane = rem & 31;
        int g = lane >> 2, tid4 = lane & 3;
        int n = j * 8 + g;
        int k0 = s * 16 + tid4 * 2;
        const float* W = which ? W2 : W1;
        __half2 bx = __floats2half2_rn(__ldg(W + k0 * DIM + n), __ldg(W + (k0 + 1) * DIM + n));
        __half2 by = __floats2half2_rn(__ldg(W + (k0 + 8) * DIM + n), __ldg(W + (k0 + 9) * DIM + n));
        uint2 u;
        u.x = *(unsigned*)&bx; u.y = *(unsigned*)&by;
        g_wfrag[which * 1024 + r] = u;
    }
}

// ---------------------------------------------------------------------------
// K1: single-launch scan (parallel predecessor poll); blk0 zeroes BN accums
// ---------------------------------------------------------------------------
__global__ void scan_kernel() {
    __shared__ int warp_sums[32];
    __shared__ int s_tot[128];
    int b = blockIdx.x, idx = b * SCAN_CHUNK + threadIdx.x;
    int d = (idx < N_NODES) ? g_deg[idx] : 0;
    int lane = threadIdx.x & 31, wid = threadIdx.x >> 5;

    int v = d;
    #pragma unroll
    for (int o = 1; o < 32; o <<= 1) { int t = __shfl_up_sync(~0u, v, o); if (lane >= o) v += t; }
    if (lane == 31) warp_sums[wid] = v;
    __syncthreads();
    if (wid == 0) {
        int s = warp_sums[lane];
        #pragma unroll
        for (int o = 1; o < 32; o <<= 1) { int t = __shfl_up_sync(~0u, s, o); if (lane >= o) s += t; }
        warp_sums[lane] = s;
    }
    __syncthreads();
    int incl = v + (wid > 0 ? warp_sums[wid - 1] : 0);
    int total = warp_sums[31];

    if (threadIdx.x == 0)
        atomicExch(&g_state[b], ((unsigned long long)(unsigned)total << 32) | 1ull);
    if (b == 0 && threadIdx.x < DIM) { g_sum[threadIdx.x] = 0.0f; g_sq[threadIdx.x] = 0.0f; }

    if (threadIdx.x < 128) s_tot[threadIdx.x] = 0;
    __syncthreads();
    if ((int)threadIdx.x < b) {
        unsigned long long st;
        do { st = *(volatile unsigned long long*)&g_state[threadIdx.x]; } while (!(st & 1ull));
        s_tot[threadIdx.x] = (int)(st >> 32);
    }
    __syncthreads();
    if (threadIdx.x < 64) s_tot[threadIdx.x] += s_tot[threadIdx.x + 64];
    __syncthreads();
    if (threadIdx.x < 32) {
        int s = s_tot[threadIdx.x] + s_tot[threadIdx.x + 32];
        #pragma unroll
        for (int o = 16; o > 0; o >>= 1) s += __shfl_down_sync(~0u, s, o);
        if (threadIdx.x == 0) s_tot[0] = s;
    }
    __syncthreads();
    int ex = s_tot[0] + incl - d;
    if (idx < N_NODES) { g_off[idx] = ex; g_cur[idx] = ex; }
}

// ---------------------------------------------------------------------------
// K2: scatter packed (attr,src) — 4 edges/thread; blk0 resets g_state
// ---------------------------------------------------------------------------
__global__ void scatter_kernel(const int* __restrict__ ei, const int* __restrict__ ea) {
    if (blockIdx.x == 0 && threadIdx.x < NCH) g_state[threadIdx.x] = 0ull;
    int i = blockIdx.x * 256 + threadIdx.x;
    if (i >= N_EDGES / 4) return;
    int4 s = ((const int4*)ei)[i];
    int4 d = ((const int4*)(ei + N_EDGES))[i];
    int4 a = ((const int4*)ea)[i];
    int p0 = atomicAdd(&g_cur[d.x], 1);
    int p1 = atomicAdd(&g_cur[d.y], 1);
    int p2 = atomicAdd(&g_cur[d.z], 1);
    int p3 = atomicAdd(&g_cur[d.w], 1);
    g_es[p0] = (unsigned)s.x | ((unsigned)a.x << 28);
    g_es[p1] = (unsigned)s.y | ((unsigned)a.y << 28);
    g_es[p2] = (unsigned)s.z | ((unsigned)a.z << 28);
    g_es[p3] = (unsigned)s.w | ((unsigned)a.w << 28);
}

// ---------------------------------------------------------------------------
// K3: aggregate — 8 lanes/node, fp16 x gather, fp32 emb/message math.
// ---------------------------------------------------------------------------
__global__ void __launch_bounds__(256)
agg_kernel(const float* __restrict__ x, const float* __restrict__ emb,
           const float* __restrict__ eps) {
    __shared__ float s_emb[4 * DIM];
    s_emb[threadIdx.x] = emb[threadIdx.x];
    __syncthreads();

    int gt = blockIdx.x * 256 + threadIdx.x;
    int n = gt >> 3, lane = gt & 7;
    if (n >= N_NODES) return;

    int off = g_off[n];
    int deg = g_deg[n];
    if (lane == 0) g_deg[n] = 0;
    float s = 1.0f + __ldg(eps);

    const float4* xp = (const float4*)(x + (size_t)n * DIM + lane * 8);
    float4 accA = __ldg(xp), accB = __ldg(xp + 1);
    accA.x *= s; accA.y *= s; accA.z *= s; accA.w *= s;
    accB.x *= s; accB.y *= s; accB.z *= s; accB.w *= s;

    const uint4* xb = (const uint4*)g_x16;

    int j = 0;
    for (; j + 4 <= deg; j += 4) {
        unsigned p[4]; uint4 r[4]; const float4* e[4];
        #pragma unroll
        for (int q = 0; q < 4; q++) p[q] = __ldg(g_es + off + j + q);
        #pragma unroll
        for (int q = 0; q < 4; q++) {
            r[q] = __ldg(xb + (size_t)(p[q] & 0x0FFFFFFFu) * 8 + lane);
            e[q] = (const float4*)(s_emb + (p[q] >> 28) * DIM + lane * 8);
        }
        #pragma unroll
        for (int q = 0; q < 4; q++) {
            float2 f0 = __half22float2(*(__half2*)&r[q].x), f1 = __half22float2(*(__half2*)&r[q].y);
            float2 f2 = __half22float2(*(__half2*)&r[q].z), f3 = __half22float2(*(__half2*)&r[q].w);
            float4 ea = e[q][0], eb = e[q][1];
            accA.x += fmaxf(f0.x + ea.x, 0.f); accA.y += fmaxf(f0.y + ea.y, 0.f);
            accA.z += fmaxf(f1.x + ea.z, 0.f); accA.w += fmaxf(f1.y + ea.w, 0.f);
            accB.x += fmaxf(f2.x + eb.x, 0.f); accB.y += fmaxf(f2.y + eb.y, 0.f);
            accB.z += fmaxf(f3.x + eb.z, 0.f); accB.w += fmaxf(f3.y + eb.w, 0.f);
        }
    }
    for (; j < deg; j++) {
        unsigned p0 = __ldg(g_es + off + j);
        uint4 r0 = __ldg(xb + (size_t)(p0 & 0x0FFFFFFFu) * 8 + lane);
        const float4* e0 = (const float4*)(s_emb + (p0 >> 28) * DIM + lane * 8);
        float2 f0 = __half22float2(*(__half2*)&r0.x), f1 = __half22float2(*(__half2*)&r0.y);
        float2 f2 = __half22float2(*(__half2*)&r0.z), f3 = __half22float2(*(__half2*)&r0.w);
        float4 ea = e0[0], eb = e0[1];
        accA.x += fmaxf(f0.x + ea.x, 0.f); accA.y += fmaxf(f0.y + ea.y, 0.f);
        accA.z += fmaxf(f1.x + ea.z, 0.f); accA.w += fmaxf(f1.y + ea.w, 0.f);
        accB.x += fmaxf(f2.x + eb.x, 0.f); accB.y += fmaxf(f2.y + eb.y, 0.f);
        accB.z += fmaxf(f3.x + eb.z, 0.f); accB.w += fmaxf(f3.y + eb.w, 0.f);
    }

    float4* hp = (float4*)(g_h + (size_t)n * DIM + lane * 8);
    hp[0] = accA; hp[1] = accB;
}

// ---------------------------------------------------------------------------
// K4/K5: HMMA GEMM (mma.sync.m16n8k16), 256 threads, 128-row tile.
// Each warp: 16 rows x 64 cols = 4 k-steps x (ldmatrix.x4 + 8 mma).
// MODE 0: t = h@W1 + b1, BN stats. MODE 1: out = relu(t*A+B)@W2 + b2.
// ---------------------------------------------------------------------------
#define A_STRIDE 72   // halves per row (128B padded to 144B rows, 16B aligned)

template <int MODE>
__global__ void __launch_bounds__(256)
gemm_mma(const float* __restrict__ bias, const float* __restrict__ gamma,
         const float* __restrict__ beta, float* __restrict__ out_ext) {
    __shared__ __align__(16) __half sA[128 * A_STRIDE];   // 18432 B
    __shared__ uint2 sFrag[1024];                          // 8192 B
    __shared__ float sBias[64], sAff[128], sSum[64], sSq[64];

    int t = threadIdx.x;
    int r0 = blockIdx.x * TILE_R;
    const float* in = (MODE == 0) ? g_h : g_t;
    float* out = (MODE == 0) ? g_t : out_ext;

    if (t < 64) {
        sBias[t] = __ldg(bias + t);
        sSum[t] = 0.0f; sSq[t] = 0.0f;
        if (MODE == 1) {
            const float inv = 1.0f / (float)N_NODES;
            float mu = g_sum[t] * inv, var = g_sq[t] * inv - mu * mu;
            float a = gamma[t] * rsqrtf(var + 1e-5f);
            sAff[t] = a; sAff[64 + t] = fmaf(-mu, a, beta[t]);
        }
    }
    // copy B fragments (1024 uint2)
    {
        const uint2* src = g_wfrag + (MODE == 0 ? 0 : 1024);
        #pragma unroll
        for (int q = 0; q < 4; q++) sFrag[t + 256 * q] = __ldg(src + t + 256 * q);
    }
    if (MODE == 1) __syncthreads();   // sAff ready before staging uses it

    // stage A: 2 threads/row, 32 floats each -> fp16
    {
        int row_l = t >> 1, half = t & 1;
        int row = r0 + row_l;
        bool valid = row < N_NODES;
        const float4* rp = (const float4*)(in + (size_t)row * DIM + half * 32);
        __half* dst = sA + row_l * A_STRIDE + half * 32;
        #pragma unroll
        for (int q = 0; q < 8; q++) {
            float4 v = valid ? __ldg(rp + q) : make_float4(0.f, 0.f, 0.f, 0.f);
            if (MODE == 1) {
                int k0 = half * 32 + q * 4;
                v.x = fmaxf(fmaf(v.x, sAff[k0+0], sAff[64+k0+0]), 0.f);
                v.y = fmaxf(fmaf(v.y, sAff[k0+1], sAff[64+k0+1]), 0.f);
                v.z = fmaxf(fmaf(v.z, sAff[k0+2], sAff[64+k0+2]), 0.f);
                v.w = fmaxf(fmaf(v.w, sAff[k0+3], sAff[64+k0+3]), 0.f);
            }
            __half2 h0 = __floats2half2_rn(v.x, v.y), h1 = __floats2half2_rn(v.z, v.w);
            uint2 pk;
            pk.x = *(unsigned*)&h0; pk.y = *(unsigned*)&h1;
            *(uint2*)(dst + q * 4) = pk;
        }
    }
    __syncthreads();

    int wid = t >> 5, lane = t & 31;
    int m0 = wid * 16;
    int g = lane >> 2, tid4 = lane & 3;

    float acc[8][4];
    #pragma unroll
    for (int j = 0; j < 8; j++)
        #pragma unroll
        for (int c = 0; c < 4; c++) acc[j][c] = 0.0f;

    #pragma unroll
    for (int s = 0; s < 4; s++) {
        uint32_t a0, a1, a2, a3;
        uint32_t addr = smem_u32(sA + (m0 + (lane & 15)) * A_STRIDE + s * 16 + (lane >> 4) * 8);
        asm volatile("ldmatrix.sync.aligned.m8n8.x4.shared.b16 {%0,%1,%2,%3}, [%4];"
                     : "=r"(a0), "=r"(a1), "=r"(a2), "=r"(a3) : "r"(addr));
        #pragma unroll
        for (int j = 0; j < 8; j++) {
            uint2 b = sFrag[(s * 8 + j) * 32 + lane];
            asm volatile(
                "mma.sync.aligned.m16n8k16.row.col.f32.f16.f16.f32 "
                "{%0,%1,%2,%3}, {%4,%5,%6,%7}, {%8,%9}, {%0,%1,%2,%3};"
                : "+f"(acc[j][0]), "+f"(acc[j][1]), "+f"(acc[j][2]), "+f"(acc[j][3])
                : "r"(a0), "r"(a1), "r"(a2), "r"(a3), "r"(b.x), "r"(b.y));
        }
    }

    // epilogue: rows r1 = r0+m0+g, r2 = r1+8; cols n = j*8 + tid4*2
    int r1 = r0 + m0 + g, r2 = r1 + 8;
    bool v1 = r1 < N_NODES, v2 = r2 < N_NODES;
    #pragma unroll
    for (int j = 0; j < 8; j++) {
        int n = j * 8 + tid4 * 2;
        float b0 = sBias[n], b1 = sBias[n + 1];
        float v00 = acc[j][0] + b0, v01 = acc[j][1] + b1;
        float v10 = acc[j][2] + b0, v11 = acc[j][3] + b1;
        if (v1) *(float2*)(out + (size_t)r1 * DIM + n) = make_float2(v00, v01);
        if (v2) *(float2*)(out + (size_t)r2 * DIM + n) = make_float2(v10, v11);
        if (MODE == 0) {
            float su0 = (v1 ? v00 : 0.f) + (v2 ? v10 : 0.f);
            float su1 = (v1 ? v01 : 0.f) + (v2 ? v11 : 0.f);
            float sq0 = (v1 ? v00 * v00 : 0.f) + (v2 ? v10 * v10 : 0.f);
            float sq1 = (v1 ? v01 * v01 : 0.f) + (v2 ? v11 * v11 : 0.f);
            #pragma unroll
            for (int o = 16; o >= 4; o >>= 1) {
                su0 += __shfl_down_sync(~0u, su0, o);
                su1 += __shfl_down_sync(~0u, su1, o);
                sq0 += __shfl_down_sync(~0u, sq0, o);
                sq1 += __shfl_down_sync(~0u, sq1, o);
            }
            if (lane < 4) {
                int nn = j * 8 + lane * 2;
                atomicAdd(&sSum[nn], su0);
                atomicAdd(&sSum[nn + 1], su1);
                atomicAdd(&sSq[nn], sq0);
                atomicAdd(&sSq[nn + 1], sq1);
            }
        }
    }
    if (MODE == 0) {
        __syncthreads();
        if (t < 64) { atomicAdd(&g_sum[t], sSum[t]); atomicAdd(&g_sq[t], sSq[t]); }
    }
}

// ---------------------------------------------------------------------------
extern "C" void kernel_launch(void* const* d_in, const int* in_sizes, int n_in,
                              void* d_out, int out_size) {
    const float* x     = (const float*)d_in[0];
    const float* emb   = (const float*)d_in[1];
    const float* eps   = (const float*)d_in[2];
    const float* W1    = (const float*)d_in[3];
    const float* b1    = (const float*)d_in[4];
    const float* gamma = (const float*)d_in[5];
    const float* beta  = (const float*)d_in[6];
    const float* W2    = (const float*)d_in[7];
    const float* b2    = (const float*)d_in[8];
    const int*   ei    = (const int*)d_in[9];
    const int*   ea    = (const int*)d_in[10];
    float*       out   = (float*)d_out;

    prep_kernel<<<(N_NODES * DIM / 8 + 255) / 256, 256>>>(x, ei, W1, W2);
    scan_kernel<<<NCH, SCAN_CHUNK>>>();
    scatter_kernel<<<(N_EDGES / 4 + 255) / 256, 256>>>(ei, ea);
    agg_kernel<<<(N_NODES * 8 + 255) / 256, 256>>>(x, emb, eps);
    const int gblocks = (N_NODES + TILE_R - 1) / TILE_R;   // 782
    gemm_mma<0><<<gblocks, 256>>>(b1, nullptr, nullptr, nullptr);
    gemm_mma<1><<<gblocks, 256>>>(b2, gamma, beta, out);
}

// round 16
// speedup vs baseline: 1.2836x; 1.0361x over previous
#include <cuda_runtime.h>
#include <cuda_fp16.h>
#include <cstdint>

#define N_NODES 100000
#define N_EDGES 1600000
#define DIM 64
#define SCAN_CHUNK 1024
#define NCH 98
#define TILE_R 128

__device__ float  g_t[(size_t)N_NODES * DIM];
__device__ __half g_h16[(size_t)N_NODES * DIM];     // fp16 h (direct MMA A input)
__device__ __half g_x16[(size_t)N_NODES * DIM];
__device__ uint2  g_wfrag[2 * 1024];                // per-lane B fragments
__device__ float  g_sum[DIM];
__device__ float  g_sq[DIM];
__device__ int    g_deg[N_NODES];                   // zero at entry (agg resets)
__device__ int    g_off[N_NODES];
__device__ int    g_cur[N_NODES];
__device__ unsigned long long g_state[NCH];         // zero at entry (scatter resets)
__device__ unsigned g_es[N_EDGES];                  // (attr<<28) | src

__device__ __forceinline__ uint32_t smem_u32(const void* p) {
    uint32_t a;
    asm("{ .reg .u64 t; cvta.to.shared.u64 t, %1; cvt.u32.u64 %0, t; }" : "=r"(a) : "l"(p));
    return a;
}

// ---------------------------------------------------------------------------
// K0: prep — x->fp16 | dst histogram | W1/W2 -> per-lane mma B fragments.
// ---------------------------------------------------------------------------
__global__ void prep_kernel(const float* __restrict__ x, const int* __restrict__ ei,
                            const float* __restrict__ W1, const float* __restrict__ W2) {
    int i = blockIdx.x * 256 + threadIdx.x;
    if (i < N_NODES * DIM / 8) {
        float4 a = __ldg((const float4*)x + 2 * i);
        float4 b = __ldg((const float4*)x + 2 * i + 1);
        __half2 h0 = __floats2half2_rn(a.x, a.y), h1 = __floats2half2_rn(a.z, a.w);
        __half2 h2 = __floats2half2_rn(b.x, b.y), h3 = __floats2half2_rn(b.z, b.w);
        uint4 p;
        p.x = *(unsigned*)&h0; p.y = *(unsigned*)&h1;
        p.z = *(unsigned*)&h2; p.w = *(unsigned*)&h3;
        ((uint4*)g_x16)[i] = p;
    }
    if (i < N_EDGES / 4) {
        int4 d = ((const int4*)(ei + N_EDGES))[i];
        atomicAdd(&g_deg[d.x], 1); atomicAdd(&g_deg[d.y], 1);
        atomicAdd(&g_deg[d.z], 1); atomicAdd(&g_deg[d.w], 1);
    }
    if (i < 2048) {   // B frag: lane g=lane>>2, tid4=lane&3; n=j*8+g; k0=s*16+tid4*2
        int which = i >> 10, r = i & 1023;
        int s = r >> 8, rem = r & 255, j = rem >> 5, lane = rem & 31;
        int g = lane >> 2, tid4 = lane & 3;
        int n = j * 8 + g;
        int k0 = s * 16 + tid4 * 2;
        const float* W = which ? W2 : W1;
        __half2 bx = __floats2half2_rn(__ldg(W + k0 * DIM + n), __ldg(W + (k0 + 1) * DIM + n));
        __half2 by = __floats2half2_rn(__ldg(W + (k0 + 8) * DIM + n), __ldg(W + (k0 + 9) * DIM + n));
        uint2 u;
        u.x = *(unsigned*)&bx; u.y = *(unsigned*)&by;
        g_wfrag[which * 1024 + r] = u;
    }
}

// ---------------------------------------------------------------------------
// K1: single-launch scan (parallel predecessor poll); blk0 zeroes BN accums
// ---------------------------------------------------------------------------
__global__ void scan_kernel() {
    __shared__ int warp_sums[32];
    __shared__ int s_tot[128];
    int b = blockIdx.x, idx = b * SCAN_CHUNK + threadIdx.x;
    int d = (idx < N_NODES) ? g_deg[idx] : 0;
    int lane = threadIdx.x & 31, wid = threadIdx.x >> 5;

    int v = d;
    #pragma unroll
    for (int o = 1; o < 32; o <<= 1) { int t = __shfl_up_sync(~0u, v, o); if (lane >= o) v += t; }
    if (lane == 31) warp_sums[wid] = v;
    __syncthreads();
    if (wid == 0) {
        int s = warp_sums[lane];
        #pragma unroll
        for (int o = 1; o < 32; o <<= 1) { int t = __shfl_up_sync(~0u, s, o); if (lane >= o) s += t; }
        warp_sums[lane] = s;
    }
    __syncthreads();
    int incl = v + (wid > 0 ? warp_sums[wid - 1] : 0);
    int total = warp_sums[31];

    if (threadIdx.x == 0)
        atomicExch(&g_state[b], ((unsigned long long)(unsigned)total << 32) | 1ull);
    if (b == 0 && threadIdx.x < DIM) { g_sum[threadIdx.x] = 0.0f; g_sq[threadIdx.x] = 0.0f; }

    if (threadIdx.x < 128) s_tot[threadIdx.x] = 0;
    __syncthreads();
    if ((int)threadIdx.x < b) {
        unsigned long long st;
        do { st = *(volatile unsigned long long*)&g_state[threadIdx.x]; } while (!(st & 1ull));
        s_tot[threadIdx.x] = (int)(st >> 32);
    }
    __syncthreads();
    if (threadIdx.x < 64) s_tot[threadIdx.x] += s_tot[threadIdx.x + 64];
    __syncthreads();
    if (threadIdx.x < 32) {
        int s = s_tot[threadIdx.x] + s_tot[threadIdx.x + 32];
        #pragma unroll
        for (int o = 16; o > 0; o >>= 1) s += __shfl_down_sync(~0u, s, o);
        if (threadIdx.x == 0) s_tot[0] = s;
    }
    __syncthreads();
    int ex = s_tot[0] + incl - d;
    if (idx < N_NODES) { g_off[idx] = ex; g_cur[idx] = ex; }
}

// ---------------------------------------------------------------------------
// K2: scatter packed (attr,src) — 4 edges/thread; blk0 resets g_state
// ---------------------------------------------------------------------------
__global__ void scatter_kernel(const int* __restrict__ ei, const int* __restrict__ ea) {
    if (blockIdx.x == 0 && threadIdx.x < NCH) g_state[threadIdx.x] = 0ull;
    int i = blockIdx.x * 256 + threadIdx.x;
    if (i >= N_EDGES / 4) return;
    int4 s = ((const int4*)ei)[i];
    int4 d = ((const int4*)(ei + N_EDGES))[i];
    int4 a = ((const int4*)ea)[i];
    int p0 = atomicAdd(&g_cur[d.x], 1);
    int p1 = atomicAdd(&g_cur[d.y], 1);
    int p2 = atomicAdd(&g_cur[d.z], 1);
    int p3 = atomicAdd(&g_cur[d.w], 1);
    g_es[p0] = (unsigned)s.x | ((unsigned)a.x << 28);
    g_es[p1] = (unsigned)s.y | ((unsigned)a.y << 28);
    g_es[p2] = (unsigned)s.z | ((unsigned)a.z << 28);
    g_es[p3] = (unsigned)s.w | ((unsigned)a.w << 28);
}

// ---------------------------------------------------------------------------
// K3: aggregate — 8 lanes/node, fp16 x gather, fp32 emb/message math.
// Stores h as fp16 (identical quantization to the MMA staging that followed).
// ---------------------------------------------------------------------------
__global__ void __launch_bounds__(256)
agg_kernel(const float* __restrict__ x, const float* __restrict__ emb,
           const float* __restrict__ eps) {
    __shared__ float s_emb[4 * DIM];
    s_emb[threadIdx.x] = emb[threadIdx.x];
    __syncthreads();

    int gt = blockIdx.x * 256 + threadIdx.x;
    int n = gt >> 3, lane = gt & 7;
    if (n >= N_NODES) return;

    int off = g_off[n];
    int deg = g_deg[n];
    if (lane == 0) g_deg[n] = 0;
    float s = 1.0f + __ldg(eps);

    const float4* xp = (const float4*)(x + (size_t)n * DIM + lane * 8);
    float4 accA = __ldg(xp), accB = __ldg(xp + 1);
    accA.x *= s; accA.y *= s; accA.z *= s; accA.w *= s;
    accB.x *= s; accB.y *= s; accB.z *= s; accB.w *= s;

    const uint4* xb = (const uint4*)g_x16;

    int j = 0;
    for (; j + 4 <= deg; j += 4) {
        unsigned p[4]; uint4 r[4]; const float4* e[4];
        #pragma unroll
        for (int q = 0; q < 4; q++) p[q] = __ldg(g_es + off + j + q);
        #pragma unroll
        for (int q = 0; q < 4; q++) {
            r[q] = __ldg(xb + (size_t)(p[q] & 0x0FFFFFFFu) * 8 + lane);
            e[q] = (const float4*)(s_emb + (p[q] >> 28) * DIM + lane * 8);
        }
        #pragma unroll
        for (int q = 0; q < 4; q++) {
            float2 f0 = __half22float2(*(__half2*)&r[q].x), f1 = __half22float2(*(__half2*)&r[q].y);
            float2 f2 = __half22float2(*(__half2*)&r[q].z), f3 = __half22float2(*(__half2*)&r[q].w);
            float4 ea = e[q][0], eb = e[q][1];
            accA.x += fmaxf(f0.x + ea.x, 0.f); accA.y += fmaxf(f0.y + ea.y, 0.f);
            accA.z += fmaxf(f1.x + ea.z, 0.f); accA.w += fmaxf(f1.y + ea.w, 0.f);
            accB.x += fmaxf(f2.x + eb.x, 0.f); accB.y += fmaxf(f2.y + eb.y, 0.f);
            accB.z += fmaxf(f3.x + eb.z, 0.f); accB.w += fmaxf(f3.y + eb.w, 0.f);
        }
    }
    for (; j < deg; j++) {
        unsigned p0 = __ldg(g_es + off + j);
        uint4 r0 = __ldg(xb + (size_t)(p0 & 0x0FFFFFFFu) * 8 + lane);
        const float4* e0 = (const float4*)(s_emb + (p0 >> 28) * DIM + lane * 8);
        float2 f0 = __half22float2(*(__half2*)&r0.x), f1 = __half22float2(*(__half2*)&r0.y);
        float2 f2 = __half22float2(*(__half2*)&r0.z), f3 = __half22float2(*(__half2*)&r0.w);
        float4 ea = e0[0], eb = e0[1];
        accA.x += fmaxf(f0.x + ea.x, 0.f); accA.y += fmaxf(f0.y + ea.y, 0.f);
        accA.z += fmaxf(f1.x + ea.z, 0.f); accA.w += fmaxf(f1.y + ea.w, 0.f);
        accB.x += fmaxf(f2.x + eb.x, 0.f); accB.y += fmaxf(f2.y + eb.y, 0.f);
        accB.z += fmaxf(f3.x + eb.z, 0.f); accB.w += fmaxf(f3.y + eb.w, 0.f);
    }

    __half2 h0 = __floats2half2_rn(accA.x, accA.y), h1 = __floats2half2_rn(accA.z, accA.w);
    __half2 h2 = __floats2half2_rn(accB.x, accB.y), h3 = __floats2half2_rn(accB.z, accB.w);
    uint4 pk;
    pk.x = *(unsigned*)&h0; pk.y = *(unsigned*)&h1;
    pk.z = *(unsigned*)&h2; pk.w = *(unsigned*)&h3;
    *(uint4*)(g_h16 + (size_t)n * DIM + lane * 8) = pk;
}

// ---------------------------------------------------------------------------
// K4/K5: HMMA GEMM (mma.sync.m16n8k16), 256 threads, 128-row tile.
// MODE 0: A = g_h16 (raw fp16 copy). MODE 1: A = relu(g_t*aff) -> fp16.
// ---------------------------------------------------------------------------
#define A_STRIDE 72

template <int MODE>
__global__ void __launch_bounds__(256)
gemm_mma(const float* __restrict__ bias, const float* __restrict__ gamma,
         const float* __restrict__ beta, float* __restrict__ out_ext) {
    __shared__ __align__(16) __half sA[128 * A_STRIDE];
    __shared__ uint2 sFrag[1024];
    __shared__ float sBias[64], sAff[128], sSum[64], sSq[64];

    int t = threadIdx.x;
    int r0 = blockIdx.x * TILE_R;
    float* out = (MODE == 0) ? g_t : out_ext;

    if (t < 64) {
        sBias[t] = __ldg(bias + t);
        sSum[t] = 0.0f; sSq[t] = 0.0f;
        if (MODE == 1) {
            const float inv = 1.0f / (float)N_NODES;
            float mu = g_sum[t] * inv, var = g_sq[t] * inv - mu * mu;
            float a = gamma[t] * rsqrtf(var + 1e-5f);
            sAff[t] = a; sAff[64 + t] = fmaf(-mu, a, beta[t]);
        }
    }
    {
        const uint2* src = g_wfrag + (MODE == 0 ? 0 : 1024);
        #pragma unroll
        for (int q = 0; q < 4; q++) sFrag[t + 256 * q] = __ldg(src + t + 256 * q);
    }
    if (MODE == 1) __syncthreads();   // sAff before staging

    if (MODE == 0) {
        // stage A: raw fp16 copy, 2 threads/row x 4 uint4
        int row_l = t >> 1, half = t & 1;
        int row = r0 + row_l;
        bool valid = row < N_NODES;
        const uint4* rp = (const uint4*)(g_h16 + (size_t)row * DIM + half * 32);
        uint4* dst = (uint4*)(sA + row_l * A_STRIDE + half * 32);
        #pragma unroll
        for (int q = 0; q < 4; q++)
            dst[q] = valid ? __ldg(rp + q) : make_uint4(0, 0, 0, 0);
    } else {
        // stage A: fp32 t -> affine+relu -> fp16
        int row_l = t >> 1, half = t & 1;
        int row = r0 + row_l;
        bool valid = row < N_NODES;
        const float4* rp = (const float4*)(g_t + (size_t)row * DIM + half * 32);
        __half* dst = sA + row_l * A_STRIDE + half * 32;
        #pragma unroll
        for (int q = 0; q < 8; q++) {
            float4 v = valid ? __ldg(rp + q) : make_float4(0.f, 0.f, 0.f, 0.f);
            int k0 = half * 32 + q * 4;
            v.x = fmaxf(fmaf(v.x, sAff[k0+0], sAff[64+k0+0]), 0.f);
            v.y = fmaxf(fmaf(v.y, sAff[k0+1], sAff[64+k0+1]), 0.f);
            v.z = fmaxf(fmaf(v.z, sAff[k0+2], sAff[64+k0+2]), 0.f);
            v.w = fmaxf(fmaf(v.w, sAff[k0+3], sAff[64+k0+3]), 0.f);
            __half2 h0 = __floats2half2_rn(v.x, v.y), h1 = __floats2half2_rn(v.z, v.w);
            uint2 pk;
            pk.x = *(unsigned*)&h0; pk.y = *(unsigned*)&h1;
            *(uint2*)(dst + q * 4) = pk;
        }
    }
    __syncthreads();

    int wid = t >> 5, lane = t & 31;
    int m0 = wid * 16;
    int g = lane >> 2, tid4 = lane & 3;

    float acc[8][4];
    #pragma unroll
    for (int j = 0; j < 8; j++)
        #pragma unroll
        for (int c = 0; c < 4; c++) acc[j][c] = 0.0f;

    #pragma unroll
    for (int s = 0; s < 4; s++) {
        uint32_t a0, a1, a2, a3;
        uint32_t addr = smem_u32(sA + (m0 + (lane & 15)) * A_STRIDE + s * 16 + (lane >> 4) * 8);
        asm volatile("ldmatrix.sync.aligned.m8n8.x4.shared.b16 {%0,%1,%2,%3}, [%4];"
                     : "=r"(a0), "=r"(a1), "=r"(a2), "=r"(a3) : "r"(addr));
        #pragma unroll
        for (int j = 0; j < 8; j++) {
            uint2 b = sFrag[(s * 8 + j) * 32 + lane];
            asm volatile(
                "mma.sync.aligned.m16n8k16.row.col.f32.f16.f16.f32 "
                "{%0,%1,%2,%3}, {%4,%5,%6,%7}, {%8,%9}, {%0,%1,%2,%3};"
                : "+f"(acc[j][0]), "+f"(acc[j][1]), "+f"(acc[j][2]), "+f"(acc[j][3])
                : "r"(a0), "r"(a1), "r"(a2), "r"(a3), "r"(b.x), "r"(b.y));
        }
    }

    int r1 = r0 + m0 + g, r2 = r1 + 8;
    bool v1 = r1 < N_NODES, v2 = r2 < N_NODES;
    #pragma unroll
    for (int j = 0; j < 8; j++) {
        int n = j * 8 + tid4 * 2;
        float b0 = sBias[n], b1 = sBias[n + 1];
        float v00 = acc[j][0] + b0, v01 = acc[j][1] + b1;
        float v10 = acc[j][2] + b0, v11 = acc[j][3] + b1;
        if (v1) *(float2*)(out + (size_t)r1 * DIM + n) = make_float2(v00, v01);
        if (v2) *(float2*)(out + (size_t)r2 * DIM + n) = make_float2(v10, v11);
        if (MODE == 0) {
            float su0 = (v1 ? v00 : 0.f) + (v2 ? v10 : 0.f);
            float su1 = (v1 ? v01 : 0.f) + (v2 ? v11 : 0.f);
            float sq0 = (v1 ? v00 * v00 : 0.f) + (v2 ? v10 * v10 : 0.f);
            float sq1 = (v1 ? v01 * v01 : 0.f) + (v2 ? v11 * v11 : 0.f);
            #pragma unroll
            for (int o = 16; o >= 4; o >>= 1) {
                su0 += __shfl_down_sync(~0u, su0, o);
                su1 += __shfl_down_sync(~0u, su1, o);
                sq0 += __shfl_down_sync(~0u, sq0, o);
                sq1 += __shfl_down_sync(~0u, sq1, o);
            }
            if (lane < 4) {
                int nn = j * 8 + lane * 2;
                atomicAdd(&sSum[nn], su0);
                atomicAdd(&sSum[nn + 1], su1);
                atomicAdd(&sSq[nn], sq0);
                atomicAdd(&sSq[nn + 1], sq1);
            }
        }
    }
    if (MODE == 0) {
        __syncthreads();
        if (t < 64) { atomicAdd(&g_sum[t], sSum[t]); atomicAdd(&g_sq[t], sSq[t]); }
    }
}

// ---------------------------------------------------------------------------
extern "C" void kernel_launch(void* const* d_in, const int* in_sizes, int n_in,
                              void* d_out, int out_size) {
    const float* x     = (const float*)d_in[0];
    const float* emb   = (const float*)d_in[1];
    const float* eps   = (const float*)d_in[2];
    const float* W1    = (const float*)d_in[3];
    const float* b1    = (const float*)d_in[4];
    const float* gamma = (const float*)d_in[5];
    const float* beta  = (const float*)d_in[6];
    const float* W2    = (const float*)d_in[7];
    const float* b2    = (const float*)d_in[8];
    const int*   ei    = (const int*)d_in[9];
    const int*   ea    = (const int*)d_in[10];
    float*       out   = (float*)d_out;

    prep_kernel<<<(N_NODES * DIM / 8 + 255) / 256, 256>>>(x, ei, W1, W2);
    scan_kernel<<<NCH, SCAN_CHUNK>>>();
    scatter_kernel<<<(N_EDGES / 4 + 255) / 256, 256>>>(ei, ea);
    agg_kernel<<<(N_NODES * 8 + 255) / 256, 256>>>(x, emb, eps);
    const int gblocks = (N_NODES + TILE_R - 1) / TILE_R;   // 782
    gemm_mma<0><<<gblocks, 256>>>(b1, nullptr, nullptr, nullptr);
    gemm_mma<1><<<gblocks, 256>>>(b2, gamma, beta, out);
}